// round 1
// baseline (speedup 1.0000x reference)
#include <cuda_runtime.h>

// ---------------------------------------------------------------------------
// MultiScaleMambaEncoder — full fp32 implementation
// B=4, L=256, C=512, D_INNER=1024, D_STATE=16, DT_RANK=32, D_CONV=4, N_MAMBA=6
// Both layers batch to R=8192 tokens (layer0: 4 mambas x 4 seq x 512;
// layer1: 2 mambas x 4 seq x 1024).
// ---------------------------------------------------------------------------

#define BB 4
#define LL 256
#define CC 512
#define DIN 1024
#define DS 16
#define RTOK 8192

// scratch (device globals; no runtime allocation)
__device__ float g_u[RTOK * CC];          // mamba input tokens
__device__ float g_xz[RTOK * 2 * DIN];    // in_proj output
__device__ float g_x[RTOK * DIN];         // conv+silu output
__device__ float g_xdbl[RTOK * 64];       // x_proj output (dt|B|C)
__device__ float g_delta[RTOK * DIN];     // delta
__device__ float g_y[RTOK * DIN];         // scan output (gated)
__device__ float g_o[RTOK * CC];          // out_proj output
__device__ float g_xf[BB * 1024 * CC];    // layer-1 forward input

__device__ __forceinline__ int wsel4(int ml, int w0, int w1, int w2, int w3) {
    return ml == 0 ? w0 : ml == 1 ? w1 : ml == 2 ? w2 : w3;
}

// ---------------------------------------------------------------------------
// build layer-0 inputs: cat = [s ; reverse(s)] per (slot, b)
// slot order: 0:x0_hw(m0) 1:x1_hw(m2) 2:x0_wh(m1) 3:x1_wh(m3)
// ---------------------------------------------------------------------------
__global__ void k_build_cat(const float* __restrict__ s0, const float* __restrict__ s1,
                            const float* __restrict__ s2, const float* __restrict__ s3) {
    int idx = blockIdx.x * blockDim.x + threadIdx.x;
    if (idx >= RTOK * CC) return;
    int c = idx & (CC - 1);
    int r = idx >> 9;
    int t = r & 511;
    int b = (r >> 9) & 3;
    int slot = r >> 11;
    const float* s = slot == 0 ? s0 : slot == 1 ? s1 : slot == 2 ? s2 : s3;
    int tt = t < 256 ? t : 511 - t;
    g_u[idx] = s[(b * 256 + tt) * CC + c];
}

// ---------------------------------------------------------------------------
// SGEMM  C[M,N] = A[M,K] * W[N,K]^T, W selected per row-group.
// 128x128 tile, BK=8, 256 threads, 8x8 per thread.
// ---------------------------------------------------------------------------
__global__ __launch_bounds__(256) void k_gemm128(
    const float* __restrict__ A, const float* __restrict__ Wb, float* __restrict__ Cm,
    int M, int N, int K, int lda, int ldb, int ldc,
    int rpg, int wstride, int w0, int w1, int w2, int w3) {
    __shared__ float As[8][132];
    __shared__ float Bs[8][132];
    const int row0 = blockIdx.y * 128;
    const int col0 = blockIdx.x * 128;
    const int wsel = wsel4(row0 / rpg, w0, w1, w2, w3);
    const float* W = Wb + (size_t)wsel * wstride;
    const int tid = threadIdx.x;
    const int tx = tid & 15, ty = tid >> 4;
    const int lr = tid >> 1;
    const int lh = (tid & 1) << 2;
    const float* Aptr = A + (size_t)(row0 + lr) * lda + lh;
    const float* Bptr = W + (size_t)(col0 + lr) * ldb + lh;

    float acc[8][8];
#pragma unroll
    for (int i = 0; i < 8; i++)
#pragma unroll
        for (int j = 0; j < 8; j++) acc[i][j] = 0.f;

    for (int k0 = 0; k0 < K; k0 += 8) {
        float4 av = *(const float4*)(Aptr + k0);
        float4 bv = *(const float4*)(Bptr + k0);
        __syncthreads();
        As[lh + 0][lr] = av.x; As[lh + 1][lr] = av.y;
        As[lh + 2][lr] = av.z; As[lh + 3][lr] = av.w;
        Bs[lh + 0][lr] = bv.x; Bs[lh + 1][lr] = bv.y;
        Bs[lh + 2][lr] = bv.z; Bs[lh + 3][lr] = bv.w;
        __syncthreads();
#pragma unroll
        for (int kk = 0; kk < 8; kk++) {
            float a[8], b[8];
            *(float4*)(a)     = *(const float4*)&As[kk][ty * 8];
            *(float4*)(a + 4) = *(const float4*)&As[kk][ty * 8 + 4];
            *(float4*)(b)     = *(const float4*)&Bs[kk][tx * 8];
            *(float4*)(b + 4) = *(const float4*)&Bs[kk][tx * 8 + 4];
#pragma unroll
            for (int i = 0; i < 8; i++)
#pragma unroll
                for (int j = 0; j < 8; j++) acc[i][j] = fmaf(a[i], b[j], acc[i][j]);
        }
    }
#pragma unroll
    for (int i = 0; i < 8; i++) {
        float* cp = Cm + (size_t)(row0 + ty * 8 + i) * ldc + col0 + tx * 8;
        *(float4*)(cp)     = make_float4(acc[i][0], acc[i][1], acc[i][2], acc[i][3]);
        *(float4*)(cp + 4) = make_float4(acc[i][4], acc[i][5], acc[i][6], acc[i][7]);
    }
}

// 64x64 tile, BK=16, 256 threads, 4x4 per thread (small-N / small-K GEMMs)
__global__ __launch_bounds__(256) void k_gemm64(
    const float* __restrict__ A, const float* __restrict__ Wb, float* __restrict__ Cm,
    int M, int N, int K, int lda, int ldb, int ldc,
    int rpg, int wstride, int w0, int w1, int w2, int w3) {
    __shared__ float As[16][68];
    __shared__ float Bs[16][68];
    const int row0 = blockIdx.y * 64;
    const int col0 = blockIdx.x * 64;
    const int wsel = wsel4(row0 / rpg, w0, w1, w2, w3);
    const float* W = Wb + (size_t)wsel * wstride;
    const int tid = threadIdx.x;
    const int tx = tid & 15, ty = tid >> 4;

    float acc[4][4];
#pragma unroll
    for (int i = 0; i < 4; i++)
#pragma unroll
        for (int j = 0; j < 4; j++) acc[i][j] = 0.f;

    for (int k0 = 0; k0 < K; k0 += 16) {
        __syncthreads();
#pragma unroll
        for (int i = 0; i < 4; i++) {
            int idx = tid + i * 256;
            int kk = idx & 15, rr = idx >> 4;
            As[kk][rr] = A[(size_t)(row0 + rr) * lda + k0 + kk];
            Bs[kk][rr] = W[(size_t)(col0 + rr) * ldb + k0 + kk];
        }
        __syncthreads();
#pragma unroll
        for (int kk = 0; kk < 16; kk++) {
            float a[4], b[4];
#pragma unroll
            for (int i = 0; i < 4; i++) a[i] = As[kk][ty * 4 + i];
#pragma unroll
            for (int j = 0; j < 4; j++) b[j] = Bs[kk][tx * 4 + j];
#pragma unroll
            for (int i = 0; i < 4; i++)
#pragma unroll
                for (int j = 0; j < 4; j++) acc[i][j] = fmaf(a[i], b[j], acc[i][j]);
        }
    }
#pragma unroll
    for (int i = 0; i < 4; i++) {
        float* cp = Cm + (size_t)(row0 + ty * 4 + i) * ldc + col0 + tx * 4;
        *(float4*)cp = make_float4(acc[i][0], acc[i][1], acc[i][2], acc[i][3]);
    }
}

// ---------------------------------------------------------------------------
// causal depthwise conv (4 taps) + bias + SiLU on x-half of xz
// ---------------------------------------------------------------------------
__global__ void k_conv(const float* __restrict__ cw, const float* __restrict__ cb,
                       int T, int rpg, int w0, int w1, int w2, int w3) {
    int idx = blockIdx.x * blockDim.x + threadIdx.x;
    if (idx >= RTOK * DIN) return;
    int d = idx & (DIN - 1);
    int r = idx >> 10;
    int t = r & (T - 1);
    int m = wsel4(r / rpg, w0, w1, w2, w3);
    const float* cwp = cw + ((size_t)m * DIN + d) * 4;
    float acc = cb[m * DIN + d];
    int base = r * (2 * DIN) + d;
#pragma unroll
    for (int k = 0; k < 4; k++) {
        int tt = t - 3 + k;
        if (tt >= 0) acc = fmaf(cwp[k], g_xz[base + (k - 3) * (2 * DIN)], acc);
    }
    float e = __expf(-acc);
    g_x[idx] = __fdividef(acc, 1.f + e);
}

// delta = softplus(delta_pre + dtb)
__global__ void k_softplus(const float* __restrict__ dtb,
                           int rpg, int w0, int w1, int w2, int w3) {
    int idx = blockIdx.x * blockDim.x + threadIdx.x;
    if (idx >= RTOK * DIN) return;
    int d = idx & (DIN - 1);
    int r = idx >> 10;
    int m = wsel4(r / rpg, w0, w1, w2, w3);
    float x = g_delta[idx] + dtb[m * DIN + d];
    float sp = (x > 15.f) ? x : __logf(1.f + __expf(x));
    g_delta[idx] = sp;
}

// ---------------------------------------------------------------------------
// selective scan: one thread per (seq, d), 16 states in registers.
// dA chain: if A[d,s] == (s+1)*A[d,0] (true for this data), one exp per step.
// Fused: +D*x skip and *silu(z) gate; writes g_y.
// ---------------------------------------------------------------------------
template <bool CHAIN>
__device__ __forceinline__ void scan_body(int rbase, int T, int d,
                                          const float Av[16], float Dv) {
    float h[16];
#pragma unroll
    for (int s = 0; s < 16; s++) h[s] = 0.f;
    for (int t = 0; t < T; t++) {
        int r = rbase + t;
        float delta = g_delta[r * DIN + d];
        float xv = g_x[r * DIN + d];
        float zv = g_xz[r * (2 * DIN) + DIN + d];
        const float4* bc = (const float4*)(g_xdbl + r * 64 + 32);
        float4 bb[4], cc[4];
#pragma unroll
        for (int q = 0; q < 4; q++) { bb[q] = bc[q]; cc[q] = bc[q + 4]; }
        const float* Bv = (const float*)bb;
        const float* Cv = (const float*)cc;
        float dx = delta * xv;
        float y0 = 0.f, y1 = 0.f, y2 = 0.f, y3 = 0.f;
        float e1 = 0.f, cur = 1.f;
        if (CHAIN) e1 = __expf(delta * Av[0]);
#pragma unroll
        for (int s = 0; s < 16; s++) {
            float dA;
            if (CHAIN) { cur *= e1; dA = cur; }
            else       { dA = __expf(delta * Av[s]); }
            h[s] = fmaf(h[s], dA, dx * Bv[s]);
            float hv = h[s] * Cv[s];
            if ((s & 3) == 0) y0 += hv;
            else if ((s & 3) == 1) y1 += hv;
            else if ((s & 3) == 2) y2 += hv;
            else y3 += hv;
        }
        float y = (y0 + y1) + (y2 + y3);
        y = fmaf(Dv, xv, y);
        float sg = __fdividef(zv, 1.f + __expf(-zv));  // silu(z)
        g_y[r * DIN + d] = y * sg;
    }
}

__global__ __launch_bounds__(128) void k_scan(const float* __restrict__ Alog,
                                              const float* __restrict__ Dp,
                                              int T, int w0, int w1, int w2, int w3) {
    int seq = blockIdx.x >> 3;
    int d = ((blockIdx.x & 7) << 7) | threadIdx.x;
    int m = wsel4(seq >> 2, w0, w1, w2, w3);  // 4 sequences per mamba group
    float Av[16];
    const float* ap = Alog + ((size_t)m * DIN + d) * 16;
#pragma unroll
    for (int s = 0; s < 16; s++) Av[s] = -__expf(ap[s]);
    bool chain = true;
#pragma unroll
    for (int s = 1; s < 16; s++)
        chain = chain &&
                (fabsf(Av[s] - (float)(s + 1) * Av[0]) <=
                 1e-3f * (float)(s + 1) * fabsf(Av[0]) + 1e-7f);
    float Dv = Dp[m * DIN + d];
    int rbase = seq * T;
    if (chain) scan_body<true>(rbase, T, d, Av, Dv);
    else       scan_body<false>(rbase, T, d, Av, Dv);
}

// ---------------------------------------------------------------------------
// layer-0 epilogue: fold fwd/bwd halves, layernorm, residual, write into xf
// ---------------------------------------------------------------------------
__global__ __launch_bounds__(128) void k_combine(
    const float* __restrict__ s0, const float* __restrict__ s1,
    const float* __restrict__ s2, const float* __restrict__ s3,
    const float* __restrict__ lnw, const float* __restrict__ lnb) {
    int blk = blockIdx.x;  // 4096 = slot(4) x b(4) x t(256)
    int t = blk & 255;
    int b = (blk >> 8) & 3;
    int slot = blk >> 10;
    const float* src = slot == 0 ? s0 : slot == 1 ? s1 : slot == 2 ? s2 : s3;
    int rowA = ((slot * 4 + b) * 512 + t) * CC;
    int rowB = ((slot * 4 + b) * 512 + (511 - t)) * CC;
    int tid = threadIdx.x;
    float v[4];
#pragma unroll
    for (int j = 0; j < 4; j++) {
        int c = tid + j * 128;
        v[j] = 0.5f * (g_o[rowA + c] + g_o[rowB + c]);
    }
    __shared__ float red[8];
    int wid = tid >> 5, lane = tid & 31;
    float s = (v[0] + v[1]) + (v[2] + v[3]);
#pragma unroll
    for (int o = 16; o; o >>= 1) s += __shfl_xor_sync(~0u, s, o);
    if (lane == 0) red[wid] = s;
    __syncthreads();
    float mean = (red[0] + red[1] + red[2] + red[3]) * (1.f / 512.f);
    float q = 0.f;
#pragma unroll
    for (int j = 0; j < 4; j++) { float dd = v[j] - mean; q = fmaf(dd, dd, q); }
#pragma unroll
    for (int o = 16; o; o >>= 1) q += __shfl_xor_sync(~0u, q, o);
    if (lane == 0) red[4 + wid] = q;
    __syncthreads();
    float var = (red[4] + red[5] + red[6] + red[7]) * (1.f / 512.f);
    float rstd = rsqrtf(var + 1e-5f);
#pragma unroll
    for (int j = 0; j < 4; j++) {
        int c = tid + j * 128;
        float o = (v[j] - mean) * rstd * lnw[c] + lnb[c] + src[(b * 256 + t) * CC + c];
        g_xf[((b * 1024) + slot * 256 + t) * CC + c] = o;
    }
}

// layer-1 inputs: forward xf (mamba4) and reversed xf (mamba5)
__global__ void k_build_l1() {
    int idx = blockIdx.x * blockDim.x + threadIdx.x;
    if (idx >= BB * 1024 * CC) return;
    int c = idx & (CC - 1);
    int rest = idx >> 9;
    int tau = rest & 1023;
    int b = rest >> 10;
    float v = g_xf[idx];
    g_u[((b * 1024) + tau) * CC + c] = v;
    g_u[(((4 + b) * 1024) + (1023 - tau)) * CC + c] = v;
}

// final: fused = 0.5*(o4 + reverse(o5)); emit as (i, b, t, c) tuple-concat
__global__ void k_final(float* __restrict__ out) {
    int idx = blockIdx.x * blockDim.x + threadIdx.x;
    if (idx >= BB * 1024 * CC) return;
    int c = idx & (CC - 1);
    int rest = idx >> 9;
    int tau = rest & 1023;
    int b = rest >> 10;
    float f = 0.5f * (g_o[((b * 1024) + tau) * CC + c] +
                      g_o[(((4 + b) * 1024) + (1023 - tau)) * CC + c]);
    int i = tau >> 8;
    int t = tau & 255;
    out[(((i * 4 + b) * 256 + t) << 9) + c] = f;
}

// ---------------------------------------------------------------------------
// host launcher
// ---------------------------------------------------------------------------
extern "C" void kernel_launch(void* const* d_in, const int* in_sizes, int n_in,
                              void* d_out, int out_size) {
    const float* x0hw = (const float*)d_in[0];
    const float* x1hw = (const float*)d_in[1];
    const float* x0wh = (const float*)d_in[2];
    const float* x1wh = (const float*)d_in[3];
    const float* in_w = (const float*)d_in[4];
    const float* cw   = (const float*)d_in[5];
    const float* cb   = (const float*)d_in[6];
    const float* xw   = (const float*)d_in[7];
    const float* dtw  = (const float*)d_in[8];
    const float* dtb  = (const float*)d_in[9];
    const float* alog = (const float*)d_in[10];
    const float* Dp   = (const float*)d_in[11];
    const float* ow   = (const float*)d_in[12];
    const float* lnw  = (const float*)d_in[13];
    const float* lnb  = (const float*)d_in[14];
    float* out = (float*)d_out;

    float *pu, *pxz, *px, *pxdbl, *pdelta, *py, *po;
    cudaGetSymbolAddress((void**)&pu, g_u);
    cudaGetSymbolAddress((void**)&pxz, g_xz);
    cudaGetSymbolAddress((void**)&px, g_x);
    cudaGetSymbolAddress((void**)&pxdbl, g_xdbl);
    cudaGetSymbolAddress((void**)&pdelta, g_delta);
    cudaGetSymbolAddress((void**)&py, g_y);
    cudaGetSymbolAddress((void**)&po, g_o);

    const int EL = RTOK * DIN;     // 8.4M
    const int EL2 = RTOK * CC;     // 4.2M
    const int ELF = BB * 1024 * CC;

    // ---------------- layer 0 (mambas 0,2,1,3 over 16 seqs of T=512) --------
    {
        const int w0 = 0, w1 = 2, w2 = 1, w3 = 3, rpg = 2048, T = 512;
        k_build_cat<<<(EL2 + 255) / 256, 256>>>(x0hw, x1hw, x0wh, x1wh);
        k_gemm128<<<dim3(2048 / 128, RTOK / 128), 256>>>(
            pu, in_w, pxz, RTOK, 2048, 512, 512, 512, 2048,
            rpg, 2048 * 512, w0, w1, w2, w3);
        k_conv<<<(EL + 255) / 256, 256>>>(cw, cb, T, rpg, w0, w1, w2, w3);
        k_gemm64<<<dim3(1, RTOK / 64), 256>>>(
            px, xw, pxdbl, RTOK, 64, 1024, 1024, 1024, 64,
            rpg, 64 * 1024, w0, w1, w2, w3);
        k_gemm64<<<dim3(1024 / 64, RTOK / 64), 256>>>(
            pxdbl, dtw, pdelta, RTOK, 1024, 32, 64, 32, 1024,
            rpg, 1024 * 32, w0, w1, w2, w3);
        k_softplus<<<(EL + 255) / 256, 256>>>(dtb, rpg, w0, w1, w2, w3);
        k_scan<<<16 * 8, 128>>>(alog, Dp, T, w0, w1, w2, w3);
        k_gemm128<<<dim3(512 / 128, RTOK / 128), 256>>>(
            py, ow, po, RTOK, 512, 1024, 1024, 1024, 512,
            rpg, 512 * 1024, w0, w1, w2, w3);
        k_combine<<<4096, 128>>>(x0hw, x1hw, x0wh, x1wh, lnw, lnb);
    }

    // ---------------- layer 1 (mambas 4,5 over 8 seqs of T=1024) ------------
    {
        const int w0 = 4, w1 = 5, w2 = 4, w3 = 5, rpg = 4096, T = 1024;
        k_build_l1<<<(ELF + 255) / 256, 256>>>();
        k_gemm128<<<dim3(2048 / 128, RTOK / 128), 256>>>(
            pu, in_w, pxz, RTOK, 2048, 512, 512, 512, 2048,
            rpg, 2048 * 512, w0, w1, w2, w3);
        k_conv<<<(EL + 255) / 256, 256>>>(cw, cb, T, rpg, w0, w1, w2, w3);
        k_gemm64<<<dim3(1, RTOK / 64), 256>>>(
            px, xw, pxdbl, RTOK, 64, 1024, 1024, 1024, 64,
            rpg, 64 * 1024, w0, w1, w2, w3);
        k_gemm64<<<dim3(1024 / 64, RTOK / 64), 256>>>(
            pxdbl, dtw, pdelta, RTOK, 1024, 32, 64, 32, 1024,
            rpg, 1024 * 32, w0, w1, w2, w3);
        k_softplus<<<(EL + 255) / 256, 256>>>(dtb, rpg, w0, w1, w2, w3);
        k_scan<<<8 * 8, 128>>>(alog, Dp, T, w0, w1, w2, w3);
        k_gemm128<<<dim3(512 / 128, RTOK / 128), 256>>>(
            py, ow, po, RTOK, 512, 1024, 1024, 1024, 512,
            rpg, 512 * 1024, w0, w1, w2, w3);
        k_final<<<(ELF + 255) / 256, 256>>>(out);
    }
}

// round 2
// speedup vs baseline: 1.0436x; 1.0436x over previous
#include <cuda_runtime.h>

// ---------------------------------------------------------------------------
// MultiScaleMambaEncoder — fp32 with packed fma.rn.f32x2 GEMMs (sm_103a)
// B=4, L=256, C=512, D_INNER=1024, D_STATE=16, DT_RANK=32, D_CONV=4, N_MAMBA=6
// ---------------------------------------------------------------------------

#define BB 4
#define LL 256
#define CC 512
#define DIN 1024
#define DS 16
#define RTOK 8192

// scratch (device globals; no runtime allocation)
__device__ float g_u[RTOK * CC];
__device__ float g_xz[RTOK * 2 * DIN];
__device__ float g_x[RTOK * DIN];
__device__ float g_xdbl[RTOK * 64];
__device__ float g_xdblp[4 * RTOK * 64];   // split-K partials for x_proj
__device__ float g_delta[RTOK * DIN];
__device__ float g_y[RTOK * DIN];
__device__ float g_o[RTOK * CC];
__device__ float g_xf[BB * 1024 * CC];

__device__ __forceinline__ int wsel4(int ml, int w0, int w1, int w2, int w3) {
    return ml == 0 ? w0 : ml == 1 ? w1 : ml == 2 ? w2 : w3;
}

#define FMA2(d, a, b) asm("fma.rn.f32x2 %0, %1, %2, %0;" : "+l"(d) : "l"(a), "l"(b))
#define DUP2(d, s)    asm("mov.b64 %0, {%1, %1};" : "=l"(d) : "f"(s))

// ---------------------------------------------------------------------------
__global__ void k_build_cat(const float* __restrict__ s0, const float* __restrict__ s1,
                            const float* __restrict__ s2, const float* __restrict__ s3) {
    int idx = blockIdx.x * blockDim.x + threadIdx.x;
    if (idx >= RTOK * CC) return;
    int c = idx & (CC - 1);
    int r = idx >> 9;
    int t = r & 511;
    int b = (r >> 9) & 3;
    int slot = r >> 11;
    const float* s = slot == 0 ? s0 : slot == 1 ? s1 : slot == 2 ? s2 : s3;
    int tt = t < 256 ? t : 511 - t;
    g_u[idx] = s[(b * 256 + tt) * CC + c];
}

// ---------------------------------------------------------------------------
// SGEMM 128x128 tile, BK=8, 256 threads, 8x8 per thread via fma.rn.f32x2
// C[M,N] = A[M,K] * W[N,K]^T, W selected per 'rpg' row-group.
// ---------------------------------------------------------------------------
__global__ __launch_bounds__(256, 2) void k_gemm128(
    const float* __restrict__ A, const float* __restrict__ Wb, float* __restrict__ Cm,
    int M, int N, int K, int lda, int ldb, int ldc,
    int rpg, int wstride, int w0, int w1, int w2, int w3) {
    __shared__ float As[8][132];
    __shared__ float Bs[8][132];
    const int row0 = blockIdx.y * 128;
    const int col0 = blockIdx.x * 128;
    const int wsel = wsel4(row0 / rpg, w0, w1, w2, w3);
    const float* W = Wb + (size_t)wsel * wstride;
    const int tid = threadIdx.x;
    const int tx = tid & 15, ty = tid >> 4;
    const int lr = tid >> 1;
    const int lh = (tid & 1) << 2;
    const float* Aptr = A + (size_t)(row0 + lr) * lda + lh;
    const float* Bptr = W + (size_t)(col0 + lr) * ldb + lh;

    unsigned long long acc[8][4];
#pragma unroll
    for (int i = 0; i < 8; i++)
#pragma unroll
        for (int j = 0; j < 4; j++) acc[i][j] = 0ull;

    for (int k0 = 0; k0 < K; k0 += 8) {
        float4 av = *(const float4*)(Aptr + k0);
        float4 bv = *(const float4*)(Bptr + k0);
        __syncthreads();
        As[lh + 0][lr] = av.x; As[lh + 1][lr] = av.y;
        As[lh + 2][lr] = av.z; As[lh + 3][lr] = av.w;
        Bs[lh + 0][lr] = bv.x; Bs[lh + 1][lr] = bv.y;
        Bs[lh + 2][lr] = bv.z; Bs[lh + 3][lr] = bv.w;
        __syncthreads();
#pragma unroll
        for (int kk = 0; kk < 8; kk++) {
            float a[8];
            *(float4*)(a)     = *(const float4*)&As[kk][ty * 8];
            *(float4*)(a + 4) = *(const float4*)&As[kk][ty * 8 + 4];
            unsigned long long b2[4];
            *(float4*)(&b2[0]) = *(const float4*)&Bs[kk][tx * 8];
            *(float4*)(&b2[2]) = *(const float4*)&Bs[kk][tx * 8 + 4];
#pragma unroll
            for (int i = 0; i < 8; i++) {
                unsigned long long ad;
                DUP2(ad, a[i]);
#pragma unroll
                for (int j = 0; j < 4; j++) FMA2(acc[i][j], ad, b2[j]);
            }
        }
    }
#pragma unroll
    for (int i = 0; i < 8; i++) {
        float* cp = Cm + (size_t)(row0 + ty * 8 + i) * ldc + col0 + tx * 8;
        *(ulonglong2*)(cp)     = make_ulonglong2(acc[i][0], acc[i][1]);
        *(ulonglong2*)(cp + 4) = make_ulonglong2(acc[i][2], acc[i][3]);
    }
}

// ---------------------------------------------------------------------------
// 64x64 tile, BK=16, 256 threads, 4x4 per thread (FFMA2). Optional K window.
// ---------------------------------------------------------------------------
__device__ __forceinline__ void gemm64_body(
    const float* A, const float* W, float* Cout,
    int K, int lda, int ldb, int ldc, int row0, int col0) {
    __shared__ float As[16][68];
    __shared__ float Bs[16][68];
    const int tid = threadIdx.x;
    const int tx = tid & 15, ty = tid >> 4;

    unsigned long long acc[4][2];
#pragma unroll
    for (int i = 0; i < 4; i++) { acc[i][0] = 0ull; acc[i][1] = 0ull; }

    for (int k0 = 0; k0 < K; k0 += 16) {
        __syncthreads();
#pragma unroll
        for (int i = 0; i < 4; i++) {
            int idx = tid + i * 256;
            int kk = idx & 15, rr = idx >> 4;
            As[kk][rr] = A[(size_t)(row0 + rr) * lda + k0 + kk];
            Bs[kk][rr] = W[(size_t)(col0 + rr) * ldb + k0 + kk];
        }
        __syncthreads();
#pragma unroll
        for (int kk = 0; kk < 16; kk++) {
            float a[4];
            *(float4*)a = *(const float4*)&As[kk][ty * 4];
            unsigned long long b2[2];
            *(float4*)b2 = *(const float4*)&Bs[kk][tx * 4];
#pragma unroll
            for (int i = 0; i < 4; i++) {
                unsigned long long ad;
                DUP2(ad, a[i]);
                FMA2(acc[i][0], ad, b2[0]);
                FMA2(acc[i][1], ad, b2[1]);
            }
        }
    }
#pragma unroll
    for (int i = 0; i < 4; i++) {
        float* cp = Cout + (size_t)(row0 + ty * 4 + i) * ldc + col0 + tx * 4;
        *(ulonglong2*)cp = make_ulonglong2(acc[i][0], acc[i][1]);
    }
}

__global__ __launch_bounds__(256) void k_gemm64(
    const float* __restrict__ A, const float* __restrict__ Wb, float* __restrict__ Cm,
    int M, int N, int K, int lda, int ldb, int ldc,
    int rpg, int wstride, int w0, int w1, int w2, int w3) {
    const int row0 = blockIdx.y * 64;
    const int col0 = blockIdx.x * 64;
    const int wsel = wsel4(row0 / rpg, w0, w1, w2, w3);
    gemm64_body(A, Wb + (size_t)wsel * wstride, Cm, K, lda, ldb, ldc, row0, col0);
}

// split-K (4-way) x_proj: each z computes K-slice [z*256, z*256+256) into partials
__global__ __launch_bounds__(256) void k_gemm64sk(
    const float* __restrict__ A, const float* __restrict__ Wb,
    int rpg, int wstride, int w0, int w1, int w2, int w3) {
    const int row0 = blockIdx.y * 64;
    const int z = blockIdx.z;
    const int wsel = wsel4(row0 / rpg, w0, w1, w2, w3);
    const float* W = Wb + (size_t)wsel * wstride + z * 256;
    gemm64_body(A + z * 256, W, g_xdblp + (size_t)z * RTOK * 64,
                256, 1024, 1024, 64, row0, 0);
}

__global__ void k_reduce4() {
    int idx = blockIdx.x * blockDim.x + threadIdx.x;
    if (idx >= RTOK * 64) return;
    const int S = RTOK * 64;
    g_xdbl[idx] = (g_xdblp[idx] + g_xdblp[idx + S]) +
                  (g_xdblp[idx + 2 * S] + g_xdblp[idx + 3 * S]);
}

// ---------------------------------------------------------------------------
__global__ void k_conv(const float* __restrict__ cw, const float* __restrict__ cb,
                       int T, int rpg, int w0, int w1, int w2, int w3) {
    int idx = blockIdx.x * blockDim.x + threadIdx.x;
    if (idx >= RTOK * DIN) return;
    int d = idx & (DIN - 1);
    int r = idx >> 10;
    int t = r & (T - 1);
    int m = wsel4(r / rpg, w0, w1, w2, w3);
    const float* cwp = cw + ((size_t)m * DIN + d) * 4;
    float acc = cb[m * DIN + d];
    int base = r * (2 * DIN) + d;
#pragma unroll
    for (int k = 0; k < 4; k++) {
        int tt = t - 3 + k;
        if (tt >= 0) acc = fmaf(cwp[k], g_xz[base + (k - 3) * (2 * DIN)], acc);
    }
    float e = __expf(-acc);
    g_x[idx] = __fdividef(acc, 1.f + e);
}

__global__ void k_softplus(const float* __restrict__ dtb,
                           int rpg, int w0, int w1, int w2, int w3) {
    int idx = blockIdx.x * blockDim.x + threadIdx.x;
    if (idx >= RTOK * DIN) return;
    int d = idx & (DIN - 1);
    int r = idx >> 10;
    int m = wsel4(r / rpg, w0, w1, w2, w3);
    float x = g_delta[idx] + dtb[m * DIN + d];
    float sp = (x > 15.f) ? x : __logf(1.f + __expf(x));
    g_delta[idx] = sp;
}

// ---------------------------------------------------------------------------
template <bool CHAIN>
__device__ __forceinline__ void scan_body(int rbase, int T, int d,
                                          const float Av[16], float Dv) {
    float h[16];
#pragma unroll
    for (int s = 0; s < 16; s++) h[s] = 0.f;
    for (int t = 0; t < T; t++) {
        int r = rbase + t;
        float delta = g_delta[r * DIN + d];
        float xv = g_x[r * DIN + d];
        float zv = g_xz[r * (2 * DIN) + DIN + d];
        const float4* bc = (const float4*)(g_xdbl + r * 64 + 32);
        float4 bb[4], cc[4];
#pragma unroll
        for (int q = 0; q < 4; q++) { bb[q] = bc[q]; cc[q] = bc[q + 4]; }
        const float* Bv = (const float*)bb;
        const float* Cv = (const float*)cc;
        float dx = delta * xv;
        float y0 = 0.f, y1 = 0.f, y2 = 0.f, y3 = 0.f;
        float e1 = 0.f, cur = 1.f;
        if (CHAIN) e1 = __expf(delta * Av[0]);
#pragma unroll
        for (int s = 0; s < 16; s++) {
            float dA;
            if (CHAIN) { cur *= e1; dA = cur; }
            else       { dA = __expf(delta * Av[s]); }
            h[s] = fmaf(h[s], dA, dx * Bv[s]);
            float hv = h[s] * Cv[s];
            if ((s & 3) == 0) y0 += hv;
            else if ((s & 3) == 1) y1 += hv;
            else if ((s & 3) == 2) y2 += hv;
            else y3 += hv;
        }
        float y = (y0 + y1) + (y2 + y3);
        y = fmaf(Dv, xv, y);
        float sg = __fdividef(zv, 1.f + __expf(-zv));
        g_y[r * DIN + d] = y * sg;
    }
}

__global__ __launch_bounds__(128) void k_scan(const float* __restrict__ Alog,
                                              const float* __restrict__ Dp,
                                              int T, int w0, int w1, int w2, int w3) {
    int seq = blockIdx.x >> 3;
    int d = ((blockIdx.x & 7) << 7) | threadIdx.x;
    int m = wsel4(seq >> 2, w0, w1, w2, w3);
    float Av[16];
    const float* ap = Alog + ((size_t)m * DIN + d) * 16;
#pragma unroll
    for (int s = 0; s < 16; s++) Av[s] = -__expf(ap[s]);
    bool chain = true;
#pragma unroll
    for (int s = 1; s < 16; s++)
        chain = chain &&
                (fabsf(Av[s] - (float)(s + 1) * Av[0]) <=
                 1e-3f * (float)(s + 1) * fabsf(Av[0]) + 1e-7f);
    float Dv = Dp[m * DIN + d];
    int rbase = seq * T;
    if (chain) scan_body<true>(rbase, T, d, Av, Dv);
    else       scan_body<false>(rbase, T, d, Av, Dv);
}

// ---------------------------------------------------------------------------
__global__ __launch_bounds__(128) void k_combine(
    const float* __restrict__ s0, const float* __restrict__ s1,
    const float* __restrict__ s2, const float* __restrict__ s3,
    const float* __restrict__ lnw, const float* __restrict__ lnb) {
    int blk = blockIdx.x;
    int t = blk & 255;
    int b = (blk >> 8) & 3;
    int slot = blk >> 10;
    const float* src = slot == 0 ? s0 : slot == 1 ? s1 : slot == 2 ? s2 : s3;
    int rowA = ((slot * 4 + b) * 512 + t) * CC;
    int rowB = ((slot * 4 + b) * 512 + (511 - t)) * CC;
    int tid = threadIdx.x;
    float v[4];
#pragma unroll
    for (int j = 0; j < 4; j++) {
        int c = tid + j * 128;
        v[j] = 0.5f * (g_o[rowA + c] + g_o[rowB + c]);
    }
    __shared__ float red[8];
    int wid = tid >> 5, lane = tid & 31;
    float s = (v[0] + v[1]) + (v[2] + v[3]);
#pragma unroll
    for (int o = 16; o; o >>= 1) s += __shfl_xor_sync(~0u, s, o);
    if (lane == 0) red[wid] = s;
    __syncthreads();
    float mean = (red[0] + red[1] + red[2] + red[3]) * (1.f / 512.f);
    float q = 0.f;
#pragma unroll
    for (int j = 0; j < 4; j++) { float dd = v[j] - mean; q = fmaf(dd, dd, q); }
#pragma unroll
    for (int o = 16; o; o >>= 1) q += __shfl_xor_sync(~0u, q, o);
    if (lane == 0) red[4 + wid] = q;
    __syncthreads();
    float var = (red[4] + red[5] + red[6] + red[7]) * (1.f / 512.f);
    float rstd = rsqrtf(var + 1e-5f);
#pragma unroll
    for (int j = 0; j < 4; j++) {
        int c = tid + j * 128;
        float o = (v[j] - mean) * rstd * lnw[c] + lnb[c] + src[(b * 256 + t) * CC + c];
        g_xf[((b * 1024) + slot * 256 + t) * CC + c] = o;
    }
}

__global__ void k_build_l1() {
    int idx = blockIdx.x * blockDim.x + threadIdx.x;
    if (idx >= BB * 1024 * CC) return;
    int c = idx & (CC - 1);
    int rest = idx >> 9;
    int tau = rest & 1023;
    int b = rest >> 10;
    float v = g_xf[idx];
    g_u[((b * 1024) + tau) * CC + c] = v;
    g_u[(((4 + b) * 1024) + (1023 - tau)) * CC + c] = v;
}

__global__ void k_final(float* __restrict__ out) {
    int idx = blockIdx.x * blockDim.x + threadIdx.x;
    if (idx >= BB * 1024 * CC) return;
    int c = idx & (CC - 1);
    int rest = idx >> 9;
    int tau = rest & 1023;
    int b = rest >> 10;
    float f = 0.5f * (g_o[((b * 1024) + tau) * CC + c] +
                      g_o[(((4 + b) * 1024) + (1023 - tau)) * CC + c]);
    int i = tau >> 8;
    int t = tau & 255;
    out[(((i * 4 + b) * 256 + t) << 9) + c] = f;
}

// ---------------------------------------------------------------------------
extern "C" void kernel_launch(void* const* d_in, const int* in_sizes, int n_in,
                              void* d_out, int out_size) {
    const float* x0hw = (const float*)d_in[0];
    const float* x1hw = (const float*)d_in[1];
    const float* x0wh = (const float*)d_in[2];
    const float* x1wh = (const float*)d_in[3];
    const float* in_w = (const float*)d_in[4];
    const float* cw   = (const float*)d_in[5];
    const float* cb   = (const float*)d_in[6];
    const float* xw   = (const float*)d_in[7];
    const float* dtw  = (const float*)d_in[8];
    const float* dtb  = (const float*)d_in[9];
    const float* alog = (const float*)d_in[10];
    const float* Dp   = (const float*)d_in[11];
    const float* ow   = (const float*)d_in[12];
    const float* lnw  = (const float*)d_in[13];
    const float* lnb  = (const float*)d_in[14];
    float* out = (float*)d_out;

    float *pu, *pxz, *px, *pxdbl, *pdelta, *py, *po;
    cudaGetSymbolAddress((void**)&pu, g_u);
    cudaGetSymbolAddress((void**)&pxz, g_xz);
    cudaGetSymbolAddress((void**)&px, g_x);
    cudaGetSymbolAddress((void**)&pxdbl, g_xdbl);
    cudaGetSymbolAddress((void**)&pdelta, g_delta);
    cudaGetSymbolAddress((void**)&py, g_y);
    cudaGetSymbolAddress((void**)&po, g_o);

    const int EL = RTOK * DIN;
    const int EL2 = RTOK * CC;
    const int ELF = BB * 1024 * CC;

    // ---------------- layer 0 ----------------
    {
        const int w0 = 0, w1 = 2, w2 = 1, w3 = 3, rpg = 2048, T = 512;
        k_build_cat<<<(EL2 + 255) / 256, 256>>>(x0hw, x1hw, x0wh, x1wh);
        k_gemm128<<<dim3(2048 / 128, RTOK / 128), 256>>>(
            pu, in_w, pxz, RTOK, 2048, 512, 512, 512, 2048,
            rpg, 2048 * 512, w0, w1, w2, w3);
        k_conv<<<(EL + 255) / 256, 256>>>(cw, cb, T, rpg, w0, w1, w2, w3);
        k_gemm64sk<<<dim3(1, RTOK / 64, 4), 256>>>(px, xw, rpg, 64 * 1024, w0, w1, w2, w3);
        k_reduce4<<<(RTOK * 64 + 255) / 256, 256>>>();
        k_gemm64<<<dim3(1024 / 64, RTOK / 64), 256>>>(
            pxdbl, dtw, pdelta, RTOK, 1024, 32, 64, 32, 1024,
            rpg, 1024 * 32, w0, w1, w2, w3);
        k_softplus<<<(EL + 255) / 256, 256>>>(dtb, rpg, w0, w1, w2, w3);
        k_scan<<<16 * 8, 128>>>(alog, Dp, T, w0, w1, w2, w3);
        k_gemm128<<<dim3(512 / 128, RTOK / 128), 256>>>(
            py, ow, po, RTOK, 512, 1024, 1024, 1024, 512,
            rpg, 512 * 1024, w0, w1, w2, w3);
        k_combine<<<4096, 128>>>(x0hw, x1hw, x0wh, x1wh, lnw, lnb);
    }

    // ---------------- layer 1 ----------------
    {
        const int w0 = 4, w1 = 5, w2 = 4, w3 = 5, rpg = 4096, T = 1024;
        k_build_l1<<<(ELF + 255) / 256, 256>>>();
        k_gemm128<<<dim3(2048 / 128, RTOK / 128), 256>>>(
            pu, in_w, pxz, RTOK, 2048, 512, 512, 512, 2048,
            rpg, 2048 * 512, w0, w1, w2, w3);
        k_conv<<<(EL + 255) / 256, 256>>>(cw, cb, T, rpg, w0, w1, w2, w3);
        k_gemm64sk<<<dim3(1, RTOK / 64, 4), 256>>>(px, xw, rpg, 64 * 1024, w0, w1, w2, w3);
        k_reduce4<<<(RTOK * 64 + 255) / 256, 256>>>();
        k_gemm64<<<dim3(1024 / 64, RTOK / 64), 256>>>(
            pxdbl, dtw, pdelta, RTOK, 1024, 32, 64, 32, 1024,
            rpg, 1024 * 32, w0, w1, w2, w3);
        k_softplus<<<(EL + 255) / 256, 256>>>(dtb, rpg, w0, w1, w2, w3);
        k_scan<<<8 * 8, 128>>>(alog, Dp, T, w0, w1, w2, w3);
        k_gemm128<<<dim3(512 / 128, RTOK / 128), 256>>>(
            py, ow, po, RTOK, 512, 1024, 1024, 1024, 512,
            rpg, 512 * 1024, w0, w1, w2, w3);
        k_final<<<(ELF + 255) / 256, 256>>>(out);
    }
}

// round 4
// speedup vs baseline: 1.4232x; 1.3638x over previous
#include <cuda_runtime.h>
#include <cuda_bf16.h>
#include <cstdint>

// ---------------------------------------------------------------------------
// MultiScaleMambaEncoder — big GEMMs on mma.sync bf16 (hi/lo x3, fp32 accum)
// B=4, L=256, C=512, D_INNER=1024, D_STATE=16, DT_RANK=32, D_CONV=4, N_MAMBA=6
// ---------------------------------------------------------------------------

#define BB 4
#define CC 512
#define DIN 1024
#define RTOK 8192

// fp32 scratch
__device__ float g_u[RTOK * CC];
__device__ float g_xz[RTOK * 2 * DIN];
__device__ float g_x[RTOK * DIN];
__device__ float g_xdbl[RTOK * 64];
__device__ float g_xdblp[4 * RTOK * 64];
__device__ float g_delta[RTOK * DIN];
__device__ float g_y[RTOK * DIN];
__device__ float g_o[RTOK * CC];
__device__ float g_xf[BB * 1024 * CC];
// bf16 hi/lo scratch
__device__ __nv_bfloat16 g_ah[RTOK * DIN];
__device__ __nv_bfloat16 g_al[RTOK * DIN];
__device__ __nv_bfloat16 g_wih[6 * 2048 * 512];
__device__ __nv_bfloat16 g_wil[6 * 2048 * 512];
__device__ __nv_bfloat16 g_woh[6 * 512 * 1024];
__device__ __nv_bfloat16 g_wol[6 * 512 * 1024];

__device__ __forceinline__ int wsel4(int ml, int w0, int w1, int w2, int w3) {
    return ml == 0 ? w0 : ml == 1 ? w1 : ml == 2 ? w2 : w3;
}

#define FMA2(d, a, b) asm("fma.rn.f32x2 %0, %1, %2, %0;" : "+l"(d) : "l"(a), "l"(b))
#define DUP2(d, s)    asm("mov.b64 %0, {%1, %1};" : "=l"(d) : "f"(s))

__device__ __forceinline__ uint32_t smem_u32(const void* p) {
    uint32_t a;
    asm("{ .reg .u64 t; cvta.to.shared.u64 t, %1; cvt.u32.u64 %0, t; }" : "=r"(a) : "l"(p));
    return a;
}
#define CP16(dst, src)  asm volatile("cp.async.cg.shared.global [%0], [%1], 16;" :: "r"(dst), "l"(src))
#define CP_COMMIT()     asm volatile("cp.async.commit_group;" ::: "memory")
#define CP_WAIT0()      asm volatile("cp.async.wait_group 0;" ::: "memory")
#define CP_WAIT1()      asm volatile("cp.async.wait_group 1;" ::: "memory")

#define LDM4(r0, r1, r2, r3, a) \
    asm volatile("ldmatrix.sync.aligned.m8n8.x4.shared.b16 {%0,%1,%2,%3}, [%4];" \
                 : "=r"(r0), "=r"(r1), "=r"(r2), "=r"(r3) : "r"(a))
#define LDM2(r0, r1, a) \
    asm volatile("ldmatrix.sync.aligned.m8n8.x2.shared.b16 {%0,%1}, [%2];" \
                 : "=r"(r0), "=r"(r1) : "r"(a))
#define MMA16816(d, a, b) \
    asm volatile("mma.sync.aligned.m16n8k16.row.col.f32.bf16.bf16.f32 " \
                 "{%0,%1,%2,%3},{%4,%5,%6,%7},{%8,%9},{%0,%1,%2,%3};" \
                 : "+f"((d)[0]), "+f"((d)[1]), "+f"((d)[2]), "+f"((d)[3]) \
                 : "r"((a)[0]), "r"((a)[1]), "r"((a)[2]), "r"((a)[3]), \
                   "r"((b)[0]), "r"((b)[1]))

// ---------------------------------------------------------------------------
// fp32 -> (bf16 hi, bf16 lo)
// ---------------------------------------------------------------------------
__global__ void k_cvt(const float* __restrict__ src, __nv_bfloat16* __restrict__ hi,
                      __nv_bfloat16* __restrict__ lo, int n) {
    int i = blockIdx.x * blockDim.x + threadIdx.x;
    if (i >= n) return;
    float v = src[i];
    __nv_bfloat16 h = __float2bfloat16(v);
    hi[i] = h;
    lo[i] = __float2bfloat16(v - __bfloat162float(h));
}

// ---------------------------------------------------------------------------
// mma.sync GEMM: C[M,N] = A[M,K] * W[N,K]^T  (bf16 hi/lo x3, fp32 accum)
// CTA tile 128x128, BK=32, 8 warps (warp tile 64x32), double-buffered cp.async.
// smem per stage: 4 sub-tiles (Ah|Al|Wh|Wl), each 128 rows x 32 bf16, row
// stride 80B (16B-aligned pad -> ldmatrix conflict-free). Stage = 40960 B.
// ---------------------------------------------------------------------------
#define MM_STAGE 40960
#define MM_TILE  10240

__global__ __launch_bounds__(256) void k_mma(
    const __nv_bfloat16* __restrict__ Ah, const __nv_bfloat16* __restrict__ Al,
    const __nv_bfloat16* __restrict__ WhB, const __nv_bfloat16* __restrict__ WlB,
    float* __restrict__ C, int K, int ldc,
    int rpg, int wstride, int w0, int w1, int w2, int w3) {
    extern __shared__ __align__(128) uint8_t smraw[];
    const uint32_t smb = smem_u32(smraw);
    const int tid = threadIdx.x;
    const int wid = tid >> 5;
    const int lane = tid & 31;
    const int wm = wid >> 2;            // 0..1 -> m offset 0/64
    const int wn = wid & 3;             // 0..3 -> n offset 0/32/64/96
    const int row0 = blockIdx.y * 128;
    const int col0 = blockIdx.x * 128;
    const int wsel = wsel4(row0 / rpg, w0, w1, w2, w3);
    const __nv_bfloat16* Wh = WhB + (size_t)wsel * wstride;
    const __nv_bfloat16* Wl = WlB + (size_t)wsel * wstride;
    const int nc = K >> 5;

    float acc[4][4][4];
#pragma unroll
    for (int i = 0; i < 4; i++)
#pragma unroll
        for (int j = 0; j < 4; j++)
#pragma unroll
            for (int q = 0; q < 4; q++) acc[i][j][q] = 0.f;

    // per-thread load slots: 8 cp16 per stage (2048 total / 256 threads)
    auto load_stage = [&](int kc, int st) {
        const int k0 = kc << 5;
        const uint32_t sb = smb + st * MM_STAGE;
#pragma unroll
        for (int p = 0; p < 8; p++) {
            int u = tid + (p << 8);
            int tile = u >> 9;
            int v = u & 511;
            int r = v >> 2, seg = v & 3;
            const __nv_bfloat16* src;
            if (tile == 0)      src = Ah + (size_t)(row0 + r) * K;
            else if (tile == 1) src = Al + (size_t)(row0 + r) * K;
            else if (tile == 2) src = Wh + (size_t)(col0 + r) * K;
            else                src = Wl + (size_t)(col0 + r) * K;
            CP16(sb + tile * MM_TILE + r * 80 + seg * 16, src + k0 + seg * 8);
        }
        CP_COMMIT();
    };

    load_stage(0, 0);

    for (int c = 0; c < nc; c++) {
        const int st = c & 1;
        const bool more = (c + 1 < nc);
        if (more) load_stage(c + 1, st ^ 1);
        if (more) CP_WAIT1(); else CP_WAIT0();
        __syncthreads();

        const uint32_t sb = smb + st * MM_STAGE;
        const uint32_t aRowByte = (uint32_t)(wm * 64 + (lane & 15)) * 80 + ((lane >> 4) << 4);
        const uint32_t bRowByte = (uint32_t)(wn * 32 + (lane & 7)) * 80 + (((lane >> 3) & 1) << 4);

#pragma unroll
        for (int ks = 0; ks < 2; ks++) {
            uint32_t ah[4][4], al[4][4], bh[4][2], bl[4][2];
            const uint32_t kb = ks * 32;
#pragma unroll
            for (int mi = 0; mi < 4; mi++) {
                uint32_t ra = sb + aRowByte + (uint32_t)mi * 16 * 80 + kb;
                LDM4(ah[mi][0], ah[mi][1], ah[mi][2], ah[mi][3], ra);
                LDM4(al[mi][0], al[mi][1], al[mi][2], al[mi][3], ra + MM_TILE);
            }
#pragma unroll
            for (int ni = 0; ni < 4; ni++) {
                uint32_t rb = sb + 2 * MM_TILE + bRowByte + (uint32_t)ni * 8 * 80 + kb;
                LDM2(bh[ni][0], bh[ni][1], rb);
                LDM2(bl[ni][0], bl[ni][1], rb + MM_TILE);
            }
#pragma unroll
            for (int mi = 0; mi < 4; mi++)
#pragma unroll
                for (int ni = 0; ni < 4; ni++) {
                    MMA16816(acc[mi][ni], ah[mi], bh[ni]);
                    MMA16816(acc[mi][ni], ah[mi], bl[ni]);
                    MMA16816(acc[mi][ni], al[mi], bh[ni]);
                }
        }
        __syncthreads();
    }

    // epilogue: fragment -> global
    const int gr = lane >> 2;
    const int gc = (lane & 3) * 2;
#pragma unroll
    for (int mi = 0; mi < 4; mi++)
#pragma unroll
        for (int ni = 0; ni < 4; ni++) {
            int row = row0 + wm * 64 + mi * 16 + gr;
            int col = col0 + wn * 32 + ni * 8 + gc;
            float* p0 = C + (size_t)row * ldc + col;
            float* p1 = C + (size_t)(row + 8) * ldc + col;
            *(float2*)p0 = make_float2(acc[mi][ni][0], acc[mi][ni][1]);
            *(float2*)p1 = make_float2(acc[mi][ni][2], acc[mi][ni][3]);
        }
}

// ---------------------------------------------------------------------------
__global__ void k_build_cat(const float* __restrict__ s0, const float* __restrict__ s1,
                            const float* __restrict__ s2, const float* __restrict__ s3) {
    int idx = blockIdx.x * blockDim.x + threadIdx.x;
    if (idx >= RTOK * CC) return;
    int c = idx & (CC - 1);
    int r = idx >> 9;
    int t = r & 511;
    int b = (r >> 9) & 3;
    int slot = r >> 11;
    const float* s = slot == 0 ? s0 : slot == 1 ? s1 : slot == 2 ? s2 : s3;
    int tt = t < 256 ? t : 511 - t;
    g_u[idx] = s[(b * 256 + tt) * CC + c];
}

// ---------------------------------------------------------------------------
// 64x64 FFMA2 GEMM (x_proj split-K + dt-proj)
// ---------------------------------------------------------------------------
__device__ __forceinline__ void gemm64_body(
    const float* A, const float* W, float* Cout,
    int K, int lda, int ldb, int ldc, int row0, int col0) {
    __shared__ float As[16][68];
    __shared__ float Bs[16][68];
    const int tid = threadIdx.x;
    const int tx = tid & 15, ty = tid >> 4;
    unsigned long long acc[4][2];
#pragma unroll
    for (int i = 0; i < 4; i++) { acc[i][0] = 0ull; acc[i][1] = 0ull; }
    for (int k0 = 0; k0 < K; k0 += 16) {
        __syncthreads();
#pragma unroll
        for (int i = 0; i < 4; i++) {
            int idx = tid + i * 256;
            int kk = idx & 15, rr = idx >> 4;
            As[kk][rr] = A[(size_t)(row0 + rr) * lda + k0 + kk];
            Bs[kk][rr] = W[(size_t)(col0 + rr) * ldb + k0 + kk];
        }
        __syncthreads();
#pragma unroll
        for (int kk = 0; kk < 16; kk++) {
            float a[4];
            *(float4*)a = *(const float4*)&As[kk][ty * 4];
            unsigned long long b2[2];
            *(float4*)b2 = *(const float4*)&Bs[kk][tx * 4];
#pragma unroll
            for (int i = 0; i < 4; i++) {
                unsigned long long ad;
                DUP2(ad, a[i]);
                FMA2(acc[i][0], ad, b2[0]);
                FMA2(acc[i][1], ad, b2[1]);
            }
        }
    }
#pragma unroll
    for (int i = 0; i < 4; i++) {
        float* cp = Cout + (size_t)(row0 + ty * 4 + i) * ldc + col0 + tx * 4;
        *(ulonglong2*)cp = make_ulonglong2(acc[i][0], acc[i][1]);
    }
}

__global__ __launch_bounds__(256) void k_gemm64(
    const float* __restrict__ A, const float* __restrict__ Wb, float* __restrict__ Cm,
    int K, int lda, int ldb, int ldc,
    int rpg, int wstride, int w0, int w1, int w2, int w3) {
    const int row0 = blockIdx.y * 64;
    const int col0 = blockIdx.x * 64;
    const int wsel = wsel4(row0 / rpg, w0, w1, w2, w3);
    gemm64_body(A, Wb + (size_t)wsel * wstride, Cm, K, lda, ldb, ldc, row0, col0);
}

__global__ __launch_bounds__(256) void k_gemm64sk(
    const float* __restrict__ A, const float* __restrict__ Wb,
    int rpg, int wstride, int w0, int w1, int w2, int w3) {
    const int row0 = blockIdx.y * 64;
    const int z = blockIdx.z;
    const int wsel = wsel4(row0 / rpg, w0, w1, w2, w3);
    const float* W = Wb + (size_t)wsel * wstride + z * 256;
    gemm64_body(A + z * 256, W, g_xdblp + (size_t)z * RTOK * 64,
                256, 1024, 1024, 64, row0, 0);
}

__global__ void k_reduce4() {
    int idx = blockIdx.x * blockDim.x + threadIdx.x;
    if (idx >= RTOK * 64) return;
    const int S = RTOK * 64;
    g_xdbl[idx] = (g_xdblp[idx] + g_xdblp[idx + S]) +
                  (g_xdblp[idx + 2 * S] + g_xdblp[idx + 3 * S]);
}

// ---------------------------------------------------------------------------
__global__ void k_conv(const float* __restrict__ cw, const float* __restrict__ cb,
                       int T, int rpg, int w0, int w1, int w2, int w3) {
    int idx = blockIdx.x * blockDim.x + threadIdx.x;
    if (idx >= RTOK * DIN) return;
    int d = idx & (DIN - 1);
    int r = idx >> 10;
    int t = r & (T - 1);
    int m = wsel4(r / rpg, w0, w1, w2, w3);
    const float* cwp = cw + ((size_t)m * DIN + d) * 4;
    float acc = cb[m * DIN + d];
    int base = r * (2 * DIN) + d;
#pragma unroll
    for (int k = 0; k < 4; k++) {
        int tt = t - 3 + k;
        if (tt >= 0) acc = fmaf(cwp[k], g_xz[base + (k - 3) * (2 * DIN)], acc);
    }
    float e = __expf(-acc);
    g_x[idx] = __fdividef(acc, 1.f + e);
}

__global__ void k_softplus(const float* __restrict__ dtb,
                           int rpg, int w0, int w1, int w2, int w3) {
    int idx = blockIdx.x * blockDim.x + threadIdx.x;
    if (idx >= RTOK * DIN) return;
    int d = idx & (DIN - 1);
    int r = idx >> 10;
    int m = wsel4(r / rpg, w0, w1, w2, w3);
    float x = g_delta[idx] + dtb[m * DIN + d];
    float sp = (x > 15.f) ? x : __logf(1.f + __expf(x));
    g_delta[idx] = sp;
}

// ---------------------------------------------------------------------------
template <bool CHAIN>
__device__ __forceinline__ void scan_body(int rbase, int T, int d,
                                          const float Av[16], float Dv) {
    float h[16];
#pragma unroll
    for (int s = 0; s < 16; s++) h[s] = 0.f;
    for (int t = 0; t < T; t++) {
        int r = rbase + t;
        float delta = g_delta[r * DIN + d];
        float xv = g_x[r * DIN + d];
        float zv = g_xz[r * (2 * DIN) + DIN + d];
        const float4* bc = (const float4*)(g_xdbl + r * 64 + 32);
        float4 bb[4], cc[4];
#pragma unroll
        for (int q = 0; q < 4; q++) { bb[q] = bc[q]; cc[q] = bc[q + 4]; }
        const float* Bv = (const float*)bb;
        const float* Cv = (const float*)cc;
        float dx = delta * xv;
        float y0 = 0.f, y1 = 0.f, y2 = 0.f, y3 = 0.f;
        float e1 = 0.f, cur = 1.f;
        if (CHAIN) e1 = __expf(delta * Av[0]);
#pragma unroll
        for (int s = 0; s < 16; s++) {
            float dA;
            if (CHAIN) { cur *= e1; dA = cur; }
            else       { dA = __expf(delta * Av[s]); }
            h[s] = fmaf(h[s], dA, dx * Bv[s]);
            float hv = h[s] * Cv[s];
            if ((s & 3) == 0) y0 += hv;
            else if ((s & 3) == 1) y1 += hv;
            else if ((s & 3) == 2) y2 += hv;
            else y3 += hv;
        }
        float y = (y0 + y1) + (y2 + y3);
        y = fmaf(Dv, xv, y);
        float sg = __fdividef(zv, 1.f + __expf(-zv));
        g_y[r * DIN + d] = y * sg;
    }
}

__global__ __launch_bounds__(128) void k_scan(const float* __restrict__ Alog,
                                              const float* __restrict__ Dp,
                                              int T, int w0, int w1, int w2, int w3) {
    int seq = blockIdx.x >> 3;
    int d = ((blockIdx.x & 7) << 7) | threadIdx.x;
    int m = wsel4(seq >> 2, w0, w1, w2, w3);
    float Av[16];
    const float* ap = Alog + ((size_t)m * DIN + d) * 16;
#pragma unroll
    for (int s = 0; s < 16; s++) Av[s] = -__expf(ap[s]);
    bool chain = true;
#pragma unroll
    for (int s = 1; s < 16; s++)
        chain = chain &&
                (fabsf(Av[s] - (float)(s + 1) * Av[0]) <=
                 1e-3f * (float)(s + 1) * fabsf(Av[0]) + 1e-7f);
    float Dv = Dp[m * DIN + d];
    int rbase = seq * T;
    if (chain) scan_body<true>(rbase, T, d, Av, Dv);
    else       scan_body<false>(rbase, T, d, Av, Dv);
}

// ---------------------------------------------------------------------------
__global__ __launch_bounds__(128) void k_combine(
    const float* __restrict__ s0, const float* __restrict__ s1,
    const float* __restrict__ s2, const float* __restrict__ s3,
    const float* __restrict__ lnw, const float* __restrict__ lnb) {
    int blk = blockIdx.x;
    int t = blk & 255;
    int b = (blk >> 8) & 3;
    int slot = blk >> 10;
    const float* src = slot == 0 ? s0 : slot == 1 ? s1 : slot == 2 ? s2 : s3;
    int rowA = ((slot * 4 + b) * 512 + t) * CC;
    int rowB = ((slot * 4 + b) * 512 + (511 - t)) * CC;
    int tid = threadIdx.x;
    float v[4];
#pragma unroll
    for (int j = 0; j < 4; j++) {
        int c = tid + j * 128;
        v[j] = 0.5f * (g_o[rowA + c] + g_o[rowB + c]);
    }
    __shared__ float red[8];
    int wid = tid >> 5, lane = tid & 31;
    float s = (v[0] + v[1]) + (v[2] + v[3]);
#pragma unroll
    for (int o = 16; o; o >>= 1) s += __shfl_xor_sync(~0u, s, o);
    if (lane == 0) red[wid] = s;
    __syncthreads();
    float mean = (red[0] + red[1] + red[2] + red[3]) * (1.f / 512.f);
    float q = 0.f;
#pragma unroll
    for (int j = 0; j < 4; j++) { float dd = v[j] - mean; q = fmaf(dd, dd, q); }
#pragma unroll
    for (int o = 16; o; o >>= 1) q += __shfl_xor_sync(~0u, q, o);
    if (lane == 0) red[4 + wid] = q;
    __syncthreads();
    float var = (red[4] + red[5] + red[6] + red[7]) * (1.f / 512.f);
    float rstd = rsqrtf(var + 1e-5f);
#pragma unroll
    for (int j = 0; j < 4; j++) {
        int c = tid + j * 128;
        float o = (v[j] - mean) * rstd * lnw[c] + lnb[c] + src[(b * 256 + t) * CC + c];
        g_xf[((b * 1024) + slot * 256 + t) * CC + c] = o;
    }
}

__global__ void k_build_l1() {
    int idx = blockIdx.x * blockDim.x + threadIdx.x;
    if (idx >= BB * 1024 * CC) return;
    int c = idx & (CC - 1);
    int rest = idx >> 9;
    int tau = rest & 1023;
    int b = rest >> 10;
    float v = g_xf[idx];
    g_u[((b * 1024) + tau) * CC + c] = v;
    g_u[(((4 + b) * 1024) + (1023 - tau)) * CC + c] = v;
}

__global__ void k_final(float* __restrict__ out) {
    int idx = blockIdx.x * blockDim.x + threadIdx.x;
    if (idx >= BB * 1024 * CC) return;
    int c = idx & (CC - 1);
    int rest = idx >> 9;
    int tau = rest & 1023;
    int b = rest >> 10;
    float f = 0.5f * (g_o[((b * 1024) + tau) * CC + c] +
                      g_o[(((4 + b) * 1024) + (1023 - tau)) * CC + c]);
    int i = tau >> 8;
    int t = tau & 255;
    out[(((i * 4 + b) * 256 + t) << 9) + c] = f;
}

// ---------------------------------------------------------------------------
extern "C" void kernel_launch(void* const* d_in, const int* in_sizes, int n_in,
                              void* d_out, int out_size) {
    const float* x0hw = (const float*)d_in[0];
    const float* x1hw = (const float*)d_in[1];
    const float* x0wh = (const float*)d_in[2];
    const float* x1wh = (const float*)d_in[3];
    const float* in_w = (const float*)d_in[4];
    const float* cw   = (const float*)d_in[5];
    const float* cb   = (const float*)d_in[6];
    const float* xw   = (const float*)d_in[7];
    const float* dtw  = (const float*)d_in[8];
    const float* dtb  = (const float*)d_in[9];
    const float* alog = (const float*)d_in[10];
    const float* Dp   = (const float*)d_in[11];
    const float* ow   = (const float*)d_in[12];
    const float* lnw  = (const float*)d_in[13];
    const float* lnb  = (const float*)d_in[14];
    float* out = (float*)d_out;

    float *pu, *pxz, *px, *pxdbl, *pdelta, *py, *po;
    cudaGetSymbolAddress((void**)&pu, g_u);
    cudaGetSymbolAddress((void**)&pxz, g_xz);
    cudaGetSymbolAddress((void**)&px, g_x);
    cudaGetSymbolAddress((void**)&pxdbl, g_xdbl);
    cudaGetSymbolAddress((void**)&pdelta, g_delta);
    cudaGetSymbolAddress((void**)&py, g_y);
    cudaGetSymbolAddress((void**)&po, g_o);
    __nv_bfloat16 *pah, *pal, *pwih, *pwil, *pwoh, *pwol;
    cudaGetSymbolAddress((void**)&pah, g_ah);
    cudaGetSymbolAddress((void**)&pal, g_al);
    cudaGetSymbolAddress((void**)&pwih, g_wih);
    cudaGetSymbolAddress((void**)&pwil, g_wil);
    cudaGetSymbolAddress((void**)&pwoh, g_woh);
    cudaGetSymbolAddress((void**)&pwol, g_wol);

    static int smem_set = 0;
    if (!smem_set) {
        cudaFuncSetAttribute(k_mma, cudaFuncAttributeMaxDynamicSharedMemorySize,
                             2 * MM_STAGE);
        smem_set = 1;
    }
    const int MMSMEM = 2 * MM_STAGE;

    const int EL = RTOK * DIN;
    const int EL2 = RTOK * CC;
    const int ELF = BB * 1024 * CC;

    // weights -> bf16 hi/lo
    k_cvt<<<(6 * 2048 * 512 + 255) / 256, 256>>>(in_w, pwih, pwil, 6 * 2048 * 512);
    k_cvt<<<(6 * 512 * 1024 + 255) / 256, 256>>>(ow, pwoh, pwol, 6 * 512 * 1024);

    // ---------------- layer 0 ----------------
    {
        const int w0 = 0, w1 = 2, w2 = 1, w3 = 3, rpg = 2048, T = 512;
        k_build_cat<<<(EL2 + 255) / 256, 256>>>(x0hw, x1hw, x0wh, x1wh);
        k_cvt<<<(EL2 + 255) / 256, 256>>>(pu, pah, pal, EL2);
        k_mma<<<dim3(2048 / 128, RTOK / 128), 256, MMSMEM>>>(
            pah, pal, pwih, pwil, pxz, 512, 2048, rpg, 2048 * 512, w0, w1, w2, w3);
        k_conv<<<(EL + 255) / 256, 256>>>(cw, cb, T, rpg, w0, w1, w2, w3);
        k_gemm64sk<<<dim3(1, RTOK / 64, 4), 256>>>(px, xw, rpg, 64 * 1024, w0, w1, w2, w3);
        k_reduce4<<<(RTOK * 64 + 255) / 256, 256>>>();
        k_gemm64<<<dim3(1024 / 64, RTOK / 64), 256>>>(
            pxdbl, dtw, pdelta, 32, 64, 32, 1024, rpg, 1024 * 32, w0, w1, w2, w3);
        k_softplus<<<(EL + 255) / 256, 256>>>(dtb, rpg, w0, w1, w2, w3);
        k_scan<<<16 * 8, 128>>>(alog, Dp, T, w0, w1, w2, w3);
        k_cvt<<<(EL + 255) / 256, 256>>>(py, pah, pal, EL);
        k_mma<<<dim3(512 / 128, RTOK / 128), 256, MMSMEM>>>(
            pah, pal, pwoh, pwol, po, 1024, 512, rpg, 512 * 1024, w0, w1, w2, w3);
        k_combine<<<4096, 128>>>(x0hw, x1hw, x0wh, x1wh, lnw, lnb);
    }

    // ---------------- layer 1 ----------------
    {
        const int w0 = 4, w1 = 5, w2 = 4, w3 = 5, rpg = 4096, T = 1024;
        k_build_l1<<<(ELF + 255) / 256, 256>>>();
        k_cvt<<<(EL2 + 255) / 256, 256>>>(pu, pah, pal, EL2);
        k_mma<<<dim3(2048 / 128, RTOK / 128), 256, MMSMEM>>>(
            pah, pal, pwih, pwil, pxz, 512, 2048, rpg, 2048 * 512, w0, w1, w2, w3);
        k_conv<<<(EL + 255) / 256, 256>>>(cw, cb, T, rpg, w0, w1, w2, w3);
        k_gemm64sk<<<dim3(1, RTOK / 64, 4), 256>>>(px, xw, rpg, 64 * 1024, w0, w1, w2, w3);
        k_reduce4<<<(RTOK * 64 + 255) / 256, 256>>>();
        k_gemm64<<<dim3(1024 / 64, RTOK / 64), 256>>>(
            pxdbl, dtw, pdelta, 32, 64, 32, 1024, rpg, 1024 * 32, w0, w1, w2, w3);
        k_softplus<<<(EL + 255) / 256, 256>>>(dtb, rpg, w0, w1, w2, w3);
        k_scan<<<8 * 8, 128>>>(alog, Dp, T, w0, w1, w2, w3);
        k_cvt<<<(EL + 255) / 256, 256>>>(py, pah, pal, EL);
        k_mma<<<dim3(512 / 128, RTOK / 128), 256, MMSMEM>>>(
            pah, pal, pwoh, pwol, po, 1024, 512, rpg, 512 * 1024, w0, w1, w2, w3);
        k_final<<<(ELF + 255) / 256, 256>>>(out);
    }
}

// round 5
// speedup vs baseline: 1.6108x; 1.1318x over previous
#include <cuda_runtime.h>
#include <cuda_bf16.h>
#include <cstdint>

// ---------------------------------------------------------------------------
// MultiScaleMambaEncoder — mma.sync bf16 hi/lo x3, fused elementwise passes
// ---------------------------------------------------------------------------

#define BB 4
#define CC 512
#define DIN 1024
#define RTOK 8192

// fp32 scratch
__device__ float g_xz[RTOK * 2 * DIN];
__device__ float g_x[RTOK * DIN];
__device__ float g_xdbl[RTOK * 64];
__device__ float g_xdblp[4 * RTOK * 64];
__device__ float g_delta[RTOK * DIN];
__device__ float g_o[RTOK * CC];
// bf16 hi/lo scratch (GEMM A operands)
__device__ __nv_bfloat16 g_ah[RTOK * DIN];
__device__ __nv_bfloat16 g_al[RTOK * DIN];
__device__ __nv_bfloat16 g_wih[6 * 2048 * 512];
__device__ __nv_bfloat16 g_wil[6 * 2048 * 512];
__device__ __nv_bfloat16 g_woh[6 * 512 * 1024];
__device__ __nv_bfloat16 g_wol[6 * 512 * 1024];

__device__ __forceinline__ int wsel4(int ml, int w0, int w1, int w2, int w3) {
    return ml == 0 ? w0 : ml == 1 ? w1 : ml == 2 ? w2 : w3;
}

#define FMA2(d, a, b) asm("fma.rn.f32x2 %0, %1, %2, %0;" : "+l"(d) : "l"(a), "l"(b))
#define DUP2(d, s)    asm("mov.b64 %0, {%1, %1};" : "=l"(d) : "f"(s))

__device__ __forceinline__ uint32_t smem_u32(const void* p) {
    uint32_t a;
    asm("{ .reg .u64 t; cvta.to.shared.u64 t, %1; cvt.u32.u64 %0, t; }" : "=r"(a) : "l"(p));
    return a;
}
#define CP16(dst, src)  asm volatile("cp.async.cg.shared.global [%0], [%1], 16;" :: "r"(dst), "l"(src))
#define CP_COMMIT()     asm volatile("cp.async.commit_group;" ::: "memory")
#define CP_WAIT0()      asm volatile("cp.async.wait_group 0;" ::: "memory")
#define CP_WAIT1()      asm volatile("cp.async.wait_group 1;" ::: "memory")

#define LDM4(r0, r1, r2, r3, a) \
    asm volatile("ldmatrix.sync.aligned.m8n8.x4.shared.b16 {%0,%1,%2,%3}, [%4];" \
                 : "=r"(r0), "=r"(r1), "=r"(r2), "=r"(r3) : "r"(a))
#define LDM2(r0, r1, a) \
    asm volatile("ldmatrix.sync.aligned.m8n8.x2.shared.b16 {%0,%1}, [%2];" \
                 : "=r"(r0), "=r"(r1) : "r"(a))
#define MMA16816(d, a, b) \
    asm volatile("mma.sync.aligned.m16n8k16.row.col.f32.bf16.bf16.f32 " \
                 "{%0,%1,%2,%3},{%4,%5,%6,%7},{%8,%9},{%0,%1,%2,%3};" \
                 : "+f"((d)[0]), "+f"((d)[1]), "+f"((d)[2]), "+f"((d)[3]) \
                 : "r"((a)[0]), "r"((a)[1]), "r"((a)[2]), "r"((a)[3]), \
                   "r"((b)[0]), "r"((b)[1]))

__device__ __forceinline__ void hilo(float v, __nv_bfloat16& h, __nv_bfloat16& l) {
    h = __float2bfloat16(v);
    l = __float2bfloat16(v - __bfloat162float(h));
}

// ---------------------------------------------------------------------------
__global__ void k_cvt(const float* __restrict__ src, __nv_bfloat16* __restrict__ hi,
                      __nv_bfloat16* __restrict__ lo, int n) {
    int i = blockIdx.x * blockDim.x + threadIdx.x;
    if (i >= n) return;
    float v = src[i];
    hilo(v, hi[i], lo[i]);
}

// layer-0 inputs (cat fwd+rev), emitted directly as bf16 hi/lo
__global__ void k_build_cat(const float* __restrict__ s0, const float* __restrict__ s1,
                            const float* __restrict__ s2, const float* __restrict__ s3) {
    int idx = blockIdx.x * blockDim.x + threadIdx.x;
    if (idx >= RTOK * CC) return;
    int c = idx & (CC - 1);
    int r = idx >> 9;
    int t = r & 511;
    int b = (r >> 9) & 3;
    int slot = r >> 11;
    const float* s = slot == 0 ? s0 : slot == 1 ? s1 : slot == 2 ? s2 : s3;
    int tt = t < 256 ? t : 511 - t;
    float v = s[(b * 256 + tt) * CC + c];
    hilo(v, g_ah[idx], g_al[idx]);
}

// ---------------------------------------------------------------------------
// mma.sync GEMM: C = A * W^T (bf16 hi/lo x3), 128x128 tile, BK=32, 3 stages
// ---------------------------------------------------------------------------
#define MM_STAGE 40960
#define MM_TILE  10240

__global__ __launch_bounds__(256) void k_mma(
    const __nv_bfloat16* __restrict__ Ah, const __nv_bfloat16* __restrict__ Al,
    const __nv_bfloat16* __restrict__ WhB, const __nv_bfloat16* __restrict__ WlB,
    float* __restrict__ C, int K, int ldc,
    int rpg, int wstride, int w0, int w1, int w2, int w3) {
    extern __shared__ __align__(128) uint8_t smraw[];
    const uint32_t smb = smem_u32(smraw);
    const int tid = threadIdx.x;
    const int wid = tid >> 5;
    const int lane = tid & 31;
    const int wm = wid >> 2;
    const int wn = wid & 3;
    const int row0 = blockIdx.y * 128;
    const int col0 = blockIdx.x * 128;
    const int wsel = wsel4(row0 / rpg, w0, w1, w2, w3);
    const __nv_bfloat16* Wh = WhB + (size_t)wsel * wstride;
    const __nv_bfloat16* Wl = WlB + (size_t)wsel * wstride;
    const int nc = K >> 5;

    float acc[4][4][4];
#pragma unroll
    for (int i = 0; i < 4; i++)
#pragma unroll
        for (int j = 0; j < 4; j++)
#pragma unroll
            for (int q = 0; q < 4; q++) acc[i][j][q] = 0.f;

    auto load_stage = [&](int kc, int st) {
        const int k0 = kc << 5;
        const uint32_t sb = smb + st * MM_STAGE;
#pragma unroll
        for (int p = 0; p < 8; p++) {
            int u = tid + (p << 8);
            int tile = u >> 9;
            int v = u & 511;
            int r = v >> 2, seg = v & 3;
            const __nv_bfloat16* src;
            if (tile == 0)      src = Ah + (size_t)(row0 + r) * K;
            else if (tile == 1) src = Al + (size_t)(row0 + r) * K;
            else if (tile == 2) src = Wh + (size_t)(col0 + r) * K;
            else                src = Wl + (size_t)(col0 + r) * K;
            CP16(sb + tile * MM_TILE + r * 80 + seg * 16, src + k0 + seg * 8);
        }
        CP_COMMIT();
    };

    load_stage(0, 0);
    if (nc > 1) load_stage(1, 1);
    int st = 0, ld = 2 % 3;

    for (int c = 0; c < nc; c++) {
        if (c + 1 < nc) CP_WAIT1(); else CP_WAIT0();
        __syncthreads();
        if (c + 2 < nc) {
            load_stage(c + 2, ld);
            ld = ld + 1 == 3 ? 0 : ld + 1;
        }

        const uint32_t sb = smb + st * MM_STAGE;
        st = st + 1 == 3 ? 0 : st + 1;
        const uint32_t aRowByte = (uint32_t)(wm * 64 + (lane & 15)) * 80 + ((lane >> 4) << 4);
        const uint32_t bRowByte = (uint32_t)(wn * 32 + (lane & 7)) * 80 + (((lane >> 3) & 1) << 4);

#pragma unroll
        for (int ks = 0; ks < 2; ks++) {
            uint32_t ah[4][4], al[4][4], bh[4][2], bl[4][2];
            const uint32_t kb = ks * 32;
#pragma unroll
            for (int mi = 0; mi < 4; mi++) {
                uint32_t ra = sb + aRowByte + (uint32_t)mi * 16 * 80 + kb;
                LDM4(ah[mi][0], ah[mi][1], ah[mi][2], ah[mi][3], ra);
                LDM4(al[mi][0], al[mi][1], al[mi][2], al[mi][3], ra + MM_TILE);
            }
#pragma unroll
            for (int ni = 0; ni < 4; ni++) {
                uint32_t rb = sb + 2 * MM_TILE + bRowByte + (uint32_t)ni * 8 * 80 + kb;
                LDM2(bh[ni][0], bh[ni][1], rb);
                LDM2(bl[ni][0], bl[ni][1], rb + MM_TILE);
            }
#pragma unroll
            for (int mi = 0; mi < 4; mi++)
#pragma unroll
                for (int ni = 0; ni < 4; ni++) {
                    MMA16816(acc[mi][ni], ah[mi], bh[ni]);
                    MMA16816(acc[mi][ni], ah[mi], bl[ni]);
                    MMA16816(acc[mi][ni], al[mi], bh[ni]);
                }
        }
    }

    const int gr = lane >> 2;
    const int gc = (lane & 3) * 2;
#pragma unroll
    for (int mi = 0; mi < 4; mi++)
#pragma unroll
        for (int ni = 0; ni < 4; ni++) {
            int row = row0 + wm * 64 + mi * 16 + gr;
            int col = col0 + wn * 32 + ni * 8 + gc;
            float* p0 = C + (size_t)row * ldc + col;
            float* p1 = C + (size_t)(row + 8) * ldc + col;
            *(float2*)p0 = make_float2(acc[mi][ni][0], acc[mi][ni][1]);
            *(float2*)p1 = make_float2(acc[mi][ni][2], acc[mi][ni][3]);
        }
}

// ---------------------------------------------------------------------------
// 64x64 FFMA2 GEMM body (x_proj split-K, dt-proj)
// ---------------------------------------------------------------------------
__device__ __forceinline__ void gemm64_accum(
    const float* A, const float* W, unsigned long long acc[4][2],
    int K, int lda, int ldb, int row0, int col0) {
    __shared__ float As[16][68];
    __shared__ float Bs[16][68];
    const int tid = threadIdx.x;
    const int tx = tid & 15, ty = tid >> 4;
    for (int k0 = 0; k0 < K; k0 += 16) {
        __syncthreads();
#pragma unroll
        for (int i = 0; i < 4; i++) {
            int idx = tid + i * 256;
            int kk = idx & 15, rr = idx >> 4;
            As[kk][rr] = A[(size_t)(row0 + rr) * lda + k0 + kk];
            Bs[kk][rr] = W[(size_t)(col0 + rr) * ldb + k0 + kk];
        }
        __syncthreads();
#pragma unroll
        for (int kk = 0; kk < 16; kk++) {
            float a[4];
            *(float4*)a = *(const float4*)&As[kk][ty * 4];
            unsigned long long b2[2];
            *(float4*)b2 = *(const float4*)&Bs[kk][tx * 4];
#pragma unroll
            for (int i = 0; i < 4; i++) {
                unsigned long long ad;
                DUP2(ad, a[i]);
                FMA2(acc[i][0], ad, b2[0]);
                FMA2(acc[i][1], ad, b2[1]);
            }
        }
    }
}

// split-K x_proj
__global__ __launch_bounds__(256) void k_gemm64sk(
    const float* __restrict__ A, const float* __restrict__ Wb,
    int rpg, int wstride, int w0, int w1, int w2, int w3) {
    const int row0 = blockIdx.y * 64;
    const int z = blockIdx.z;
    const int wsel = wsel4(row0 / rpg, w0, w1, w2, w3);
    const float* W = Wb + (size_t)wsel * wstride + z * 256;
    unsigned long long acc[4][2];
#pragma unroll
    for (int i = 0; i < 4; i++) { acc[i][0] = 0ull; acc[i][1] = 0ull; }
    gemm64_accum(A + z * 256, W, acc, 256, 1024, 1024, row0, 0);
    float* Cout = g_xdblp + (size_t)z * RTOK * 64;
    const int tx = threadIdx.x & 15, ty = threadIdx.x >> 4;
#pragma unroll
    for (int i = 0; i < 4; i++) {
        float* cp = Cout + (size_t)(row0 + ty * 4 + i) * 64 + tx * 4;
        *(ulonglong2*)cp = make_ulonglong2(acc[i][0], acc[i][1]);
    }
}

__global__ void k_reduce4() {
    int idx = blockIdx.x * blockDim.x + threadIdx.x;
    if (idx >= RTOK * 64) return;
    const int S = RTOK * 64;
    g_xdbl[idx] = (g_xdblp[idx] + g_xdblp[idx + S]) +
                  (g_xdblp[idx + 2 * S] + g_xdblp[idx + 3 * S]);
}

// dt-proj with fused +dtb and softplus -> g_delta
__global__ __launch_bounds__(256) void k_gemm64dt(
    const float* __restrict__ dtw, const float* __restrict__ dtb,
    int rpg, int w0, int w1, int w2, int w3) {
    const int row0 = blockIdx.y * 64;
    const int col0 = blockIdx.x * 64;
    const int m = wsel4(row0 / rpg, w0, w1, w2, w3);
    const float* W = dtw + (size_t)m * DIN * 32;
    unsigned long long acc[4][2];
#pragma unroll
    for (int i = 0; i < 4; i++) { acc[i][0] = 0ull; acc[i][1] = 0ull; }
    gemm64_accum(g_xdbl, W, acc, 32, 64, 32, row0, col0);
    const int tx = threadIdx.x & 15, ty = threadIdx.x >> 4;
#pragma unroll
    for (int i = 0; i < 4; i++) {
        const float* av = (const float*)acc[i];
        float r[4];
#pragma unroll
        for (int j = 0; j < 4; j++) {
            int col = col0 + tx * 4 + j;
            float x = av[j] + dtb[m * DIN + col];
            r[j] = (x > 15.f) ? x : __logf(1.f + __expf(x));
        }
        float* cp = g_delta + (size_t)(row0 + ty * 4 + i) * DIN + col0 + tx * 4;
        *(float4*)cp = make_float4(r[0], r[1], r[2], r[3]);
    }
}

// ---------------------------------------------------------------------------
// causal depthwise conv (4 taps) + bias + SiLU
// ---------------------------------------------------------------------------
__global__ void k_conv(const float* __restrict__ cw, const float* __restrict__ cb,
                       int T, int rpg, int w0, int w1, int w2, int w3) {
    int idx = blockIdx.x * blockDim.x + threadIdx.x;
    if (idx >= RTOK * DIN) return;
    int d = idx & (DIN - 1);
    int r = idx >> 10;
    int t = r & (T - 1);
    int m = wsel4(r / rpg, w0, w1, w2, w3);
    const float* cwp = cw + ((size_t)m * DIN + d) * 4;
    float acc = cb[m * DIN + d];
    int base = r * (2 * DIN) + d;
#pragma unroll
    for (int k = 0; k < 4; k++) {
        int tt = t - 3 + k;
        if (tt >= 0) acc = fmaf(cwp[k], g_xz[base + (k - 3) * (2 * DIN)], acc);
    }
    float e = __expf(-acc);
    g_x[idx] = __fdividef(acc, 1.f + e);
}

// ---------------------------------------------------------------------------
// selective scan: prefetched loads (unroll-2 reg double buffer), log-depth
// dA powers; writes gated y as bf16 hi/lo into g_ah/g_al.
// ---------------------------------------------------------------------------
template <bool CHAIN>
__device__ __forceinline__ void scan_body(int rbase, int T, int d,
                                          const float Av[16], float Dv) {
    float h[16];
#pragma unroll
    for (int s = 0; s < 16; s++) h[s] = 0.f;
    float dl[2], xl[2], zl[2];
    float4 Bq[2][4], Cq[2][4];

    auto prefetch = [&](int t, int sl) {
        int r = rbase + t;
        dl[sl] = g_delta[r * DIN + d];
        xl[sl] = g_x[r * DIN + d];
        zl[sl] = g_xz[r * (2 * DIN) + DIN + d];
        const float4* bc = (const float4*)(g_xdbl + r * 64 + 32);
#pragma unroll
        for (int q = 0; q < 4; q++) { Bq[sl][q] = bc[q]; Cq[sl][q] = bc[q + 4]; }
    };
    prefetch(0, 0);

#pragma unroll 2
    for (int t = 0; t < T; t++) {
        const int cs = t & 1;
        if (t + 1 < T) prefetch(t + 1, cs ^ 1);
        float delta = dl[cs], xv = xl[cs], zv = zl[cs];
        const float* Bv = (const float*)Bq[cs];
        const float* Cv = (const float*)Cq[cs];
        float dx = delta * xv;
        float p[16];
        if (CHAIN) {
            float e1 = __expf(delta * Av[0]);
            float e2 = e1 * e1, e4 = e2 * e2, e8 = e4 * e4;
            p[0] = e1;       p[1] = e2;       p[2] = e2 * e1;  p[3] = e4;
            p[4] = e4 * e1;  p[5] = e4 * e2;  p[6] = e4 * p[2]; p[7] = e8;
            p[8] = e8 * e1;  p[9] = e8 * e2;  p[10] = e8 * p[2]; p[11] = e8 * e4;
            p[12] = e8 * p[4]; p[13] = e8 * p[5]; p[14] = e8 * p[6]; p[15] = e8 * e8;
        } else {
#pragma unroll
            for (int s = 0; s < 16; s++) p[s] = __expf(delta * Av[s]);
        }
        float y0 = 0.f, y1 = 0.f, y2 = 0.f, y3 = 0.f;
#pragma unroll
        for (int s = 0; s < 16; s++) {
            h[s] = fmaf(h[s], p[s], dx * Bv[s]);
            float hv = h[s] * Cv[s];
            if ((s & 3) == 0) y0 += hv;
            else if ((s & 3) == 1) y1 += hv;
            else if ((s & 3) == 2) y2 += hv;
            else y3 += hv;
        }
        float y = (y0 + y1) + (y2 + y3);
        y = fmaf(Dv, xv, y);
        float sg = __fdividef(zv, 1.f + __expf(-zv));
        float yv = y * sg;
        int r = rbase + t;
        hilo(yv, g_ah[r * DIN + d], g_al[r * DIN + d]);
    }
}

__global__ __launch_bounds__(128) void k_scan(const float* __restrict__ Alog,
                                              const float* __restrict__ Dp,
                                              int T, int w0, int w1, int w2, int w3) {
    int seq = blockIdx.x >> 3;
    int d = ((blockIdx.x & 7) << 7) | threadIdx.x;
    int m = wsel4(seq >> 2, w0, w1, w2, w3);
    float Av[16];
    const float* ap = Alog + ((size_t)m * DIN + d) * 16;
#pragma unroll
    for (int s = 0; s < 16; s++) Av[s] = -__expf(ap[s]);
    bool chain = true;
#pragma unroll
    for (int s = 1; s < 16; s++)
        chain = chain &&
                (fabsf(Av[s] - (float)(s + 1) * Av[0]) <=
                 1e-3f * (float)(s + 1) * fabsf(Av[0]) + 1e-7f);
    float Dv = Dp[m * DIN + d];
    int rbase = seq * T;
    if (chain) scan_body<true>(rbase, T, d, Av, Dv);
    else       scan_body<false>(rbase, T, d, Av, Dv);
}

// ---------------------------------------------------------------------------
// layer-0 epilogue: fold halves, layernorm, residual; emit layer-1 GEMM input
// (forward + reversed copies) directly as bf16 hi/lo.
// ---------------------------------------------------------------------------
__global__ __launch_bounds__(128) void k_combine(
    const float* __restrict__ s0, const float* __restrict__ s1,
    const float* __restrict__ s2, const float* __restrict__ s3,
    const float* __restrict__ lnw, const float* __restrict__ lnb) {
    int blk = blockIdx.x;
    int t = blk & 255;
    int b = (blk >> 8) & 3;
    int slot = blk >> 10;
    const float* src = slot == 0 ? s0 : slot == 1 ? s1 : slot == 2 ? s2 : s3;
    int rowA = ((slot * 4 + b) * 512 + t) * CC;
    int rowB = ((slot * 4 + b) * 512 + (511 - t)) * CC;
    int tid = threadIdx.x;
    float v[4];
#pragma unroll
    for (int j = 0; j < 4; j++) {
        int c = tid + j * 128;
        v[j] = 0.5f * (g_o[rowA + c] + g_o[rowB + c]);
    }
    __shared__ float red[8];
    int wid = tid >> 5, lane = tid & 31;
    float s = (v[0] + v[1]) + (v[2] + v[3]);
#pragma unroll
    for (int o = 16; o; o >>= 1) s += __shfl_xor_sync(~0u, s, o);
    if (lane == 0) red[wid] = s;
    __syncthreads();
    float mean = (red[0] + red[1] + red[2] + red[3]) * (1.f / 512.f);
    float q = 0.f;
#pragma unroll
    for (int j = 0; j < 4; j++) { float dd = v[j] - mean; q = fmaf(dd, dd, q); }
#pragma unroll
    for (int o = 16; o; o >>= 1) q += __shfl_xor_sync(~0u, q, o);
    if (lane == 0) red[4 + wid] = q;
    __syncthreads();
    float var = (red[4] + red[5] + red[6] + red[7]) * (1.f / 512.f);
    float rstd = rsqrtf(var + 1e-5f);
    int tau = slot * 256 + t;
#pragma unroll
    for (int j = 0; j < 4; j++) {
        int c = tid + j * 128;
        float o = (v[j] - mean) * rstd * lnw[c] + lnb[c] + src[(b * 256 + t) * CC + c];
        __nv_bfloat16 hh, ll;
        hilo(o, hh, ll);
        int idxF = ((b * 1024) + tau) * CC + c;
        int idxR = (((4 + b) * 1024) + (1023 - tau)) * CC + c;
        g_ah[idxF] = hh; g_al[idxF] = ll;
        g_ah[idxR] = hh; g_al[idxR] = ll;
    }
}

__global__ void k_final(float* __restrict__ out) {
    int idx = blockIdx.x * blockDim.x + threadIdx.x;
    if (idx >= BB * 1024 * CC) return;
    int c = idx & (CC - 1);
    int rest = idx >> 9;
    int tau = rest & 1023;
    int b = rest >> 10;
    float f = 0.5f * (g_o[((b * 1024) + tau) * CC + c] +
                      g_o[(((4 + b) * 1024) + (1023 - tau)) * CC + c]);
    int i = tau >> 8;
    int t = tau & 255;
    out[(((i * 4 + b) * 256 + t) << 9) + c] = f;
}

// ---------------------------------------------------------------------------
extern "C" void kernel_launch(void* const* d_in, const int* in_sizes, int n_in,
                              void* d_out, int out_size) {
    const float* x0hw = (const float*)d_in[0];
    const float* x1hw = (const float*)d_in[1];
    const float* x0wh = (const float*)d_in[2];
    const float* x1wh = (const float*)d_in[3];
    const float* in_w = (const float*)d_in[4];
    const float* cw   = (const float*)d_in[5];
    const float* cb   = (const float*)d_in[6];
    const float* xw   = (const float*)d_in[7];
    const float* dtw  = (const float*)d_in[8];
    const float* dtb  = (const float*)d_in[9];
    const float* alog = (const float*)d_in[10];
    const float* Dp   = (const float*)d_in[11];
    const float* ow   = (const float*)d_in[12];
    const float* lnw  = (const float*)d_in[13];
    const float* lnb  = (const float*)d_in[14];
    float* out = (float*)d_out;

    float *pxz, *px, *po;
    cudaGetSymbolAddress((void**)&pxz, g_xz);
    cudaGetSymbolAddress((void**)&px, g_x);
    cudaGetSymbolAddress((void**)&po, g_o);
    __nv_bfloat16 *pah, *pal, *pwih, *pwil, *pwoh, *pwol;
    cudaGetSymbolAddress((void**)&pah, g_ah);
    cudaGetSymbolAddress((void**)&pal, g_al);
    cudaGetSymbolAddress((void**)&pwih, g_wih);
    cudaGetSymbolAddress((void**)&pwil, g_wil);
    cudaGetSymbolAddress((void**)&pwoh, g_woh);
    cudaGetSymbolAddress((void**)&pwol, g_wol);

    static int smem_set = 0;
    if (!smem_set) {
        cudaFuncSetAttribute(k_mma, cudaFuncAttributeMaxDynamicSharedMemorySize,
                             3 * MM_STAGE);
        smem_set = 1;
    }
    const int MMSMEM = 3 * MM_STAGE;

    const int EL = RTOK * DIN;
    const int EL2 = RTOK * CC;
    const int ELF = BB * 1024 * CC;

    // weights -> bf16 hi/lo
    k_cvt<<<(6 * 2048 * 512 + 255) / 256, 256>>>(in_w, pwih, pwil, 6 * 2048 * 512);
    k_cvt<<<(6 * 512 * 1024 + 255) / 256, 256>>>(ow, pwoh, pwol, 6 * 512 * 1024);

    // ---------------- layer 0 ----------------
    {
        const int w0 = 0, w1 = 2, w2 = 1, w3 = 3, rpg = 2048, T = 512;
        k_build_cat<<<(EL2 + 255) / 256, 256>>>(x0hw, x1hw, x0wh, x1wh);
        k_mma<<<dim3(2048 / 128, RTOK / 128), 256, MMSMEM>>>(
            pah, pal, pwih, pwil, pxz, 512, 2048, rpg, 2048 * 512, w0, w1, w2, w3);
        k_conv<<<(EL + 255) / 256, 256>>>(cw, cb, T, rpg, w0, w1, w2, w3);
        k_gemm64sk<<<dim3(1, RTOK / 64, 4), 256>>>(px, xw, rpg, 64 * 1024, w0, w1, w2, w3);
        k_reduce4<<<(RTOK * 64 + 255) / 256, 256>>>();
        k_gemm64dt<<<dim3(1024 / 64, RTOK / 64), 256>>>(dtw, dtb, rpg, w0, w1, w2, w3);
        k_scan<<<16 * 8, 128>>>(alog, Dp, T, w0, w1, w2, w3);
        k_mma<<<dim3(512 / 128, RTOK / 128), 256, MMSMEM>>>(
            pah, pal, pwoh, pwol, po, 1024, 512, rpg, 512 * 1024, w0, w1, w2, w3);
        k_combine<<<4096, 128>>>(x0hw, x1hw, x0wh, x1wh, lnw, lnb);
    }

    // ---------------- layer 1 ----------------
    {
        const int w0 = 4, w1 = 5, w2 = 4, w3 = 5, rpg = 4096, T = 1024;
        k_mma<<<dim3(2048 / 128, RTOK / 128), 256, MMSMEM>>>(
            pah, pal, pwih, pwil, pxz, 512, 2048, rpg, 2048 * 512, w0, w1, w2, w3);
        k_conv<<<(EL + 255) / 256, 256>>>(cw, cb, T, rpg, w0, w1, w2, w3);
        k_gemm64sk<<<dim3(1, RTOK / 64, 4), 256>>>(px, xw, rpg, 64 * 1024, w0, w1, w2, w3);
        k_reduce4<<<(RTOK * 64 + 255) / 256, 256>>>();
        k_gemm64dt<<<dim3(1024 / 64, RTOK / 64), 256>>>(dtw, dtb, rpg, w0, w1, w2, w3);
        k_scan<<<8 * 8, 128>>>(alog, Dp, T, w0, w1, w2, w3);
        k_mma<<<dim3(512 / 128, RTOK / 128), 256, MMSMEM>>>(
            pah, pal, pwoh, pwol, po, 1024, 512, rpg, 512 * 1024, w0, w1, w2, w3);
        k_final<<<(ELF + 255) / 256, 256>>>(out);
    }
}

// round 6
// speedup vs baseline: 1.7097x; 1.0614x over previous
#include <cuda_runtime.h>
#include <cuda_bf16.h>
#include <cstdint>

// ---------------------------------------------------------------------------
// MultiScaleMambaEncoder — mma.sync bf16 hi/lo x3 GEMMs + pipelined scan
// ---------------------------------------------------------------------------

#define BB 4
#define CC 512
#define DIN 1024
#define RTOK 8192

// fp32 scratch
__device__ float g_xz[RTOK * 2 * DIN];
__device__ float g_x[RTOK * DIN];
__device__ float g_xdbl[RTOK * 64];
__device__ float g_xdblp[4 * RTOK * 64];
__device__ float g_delta[RTOK * DIN];
__device__ float g_o[RTOK * CC];
// bf16 hi/lo scratch (GEMM A operands)
__device__ __nv_bfloat16 g_ah[RTOK * DIN];
__device__ __nv_bfloat16 g_al[RTOK * DIN];
__device__ __nv_bfloat16 g_wih[6 * 2048 * 512];
__device__ __nv_bfloat16 g_wil[6 * 2048 * 512];
__device__ __nv_bfloat16 g_woh[6 * 512 * 1024];
__device__ __nv_bfloat16 g_wol[6 * 512 * 1024];

__device__ __forceinline__ int wsel4(int ml, int w0, int w1, int w2, int w3) {
    return ml == 0 ? w0 : ml == 1 ? w1 : ml == 2 ? w2 : w3;
}

#define FMA2(d, a, b) asm("fma.rn.f32x2 %0, %1, %2, %0;" : "+l"(d) : "l"(a), "l"(b))
#define DUP2(d, s)    asm("mov.b64 %0, {%1, %1};" : "=l"(d) : "f"(s))

__device__ __forceinline__ uint32_t smem_u32(const void* p) {
    uint32_t a;
    asm("{ .reg .u64 t; cvta.to.shared.u64 t, %1; cvt.u32.u64 %0, t; }" : "=r"(a) : "l"(p));
    return a;
}
#define CP16(dst, src)  asm volatile("cp.async.cg.shared.global [%0], [%1], 16;" :: "r"(dst), "l"(src))
#define CP_COMMIT()     asm volatile("cp.async.commit_group;" ::: "memory")
#define CP_WAIT0()      asm volatile("cp.async.wait_group 0;" ::: "memory")
#define CP_WAIT6()      asm volatile("cp.async.wait_group 6;" ::: "memory")

#define LDM4(r0, r1, r2, r3, a) \
    asm volatile("ldmatrix.sync.aligned.m8n8.x4.shared.b16 {%0,%1,%2,%3}, [%4];" \
                 : "=r"(r0), "=r"(r1), "=r"(r2), "=r"(r3) : "r"(a))
#define LDM2(r0, r1, a) \
    asm volatile("ldmatrix.sync.aligned.m8n8.x2.shared.b16 {%0,%1}, [%2];" \
                 : "=r"(r0), "=r"(r1) : "r"(a))
#define MMA16816(d, a, b) \
    asm volatile("mma.sync.aligned.m16n8k16.row.col.f32.bf16.bf16.f32 " \
                 "{%0,%1,%2,%3},{%4,%5,%6,%7},{%8,%9},{%0,%1,%2,%3};" \
                 : "+f"((d)[0]), "+f"((d)[1]), "+f"((d)[2]), "+f"((d)[3]) \
                 : "r"((a)[0]), "r"((a)[1]), "r"((a)[2]), "r"((a)[3]), \
                   "r"((b)[0]), "r"((b)[1]))

__device__ __forceinline__ void hilo(float v, __nv_bfloat16& h, __nv_bfloat16& l) {
    h = __float2bfloat16(v);
    l = __float2bfloat16(v - __bfloat162float(h));
}

// ---------------------------------------------------------------------------
__global__ void k_cvt(const float* __restrict__ src, __nv_bfloat16* __restrict__ hi,
                      __nv_bfloat16* __restrict__ lo, int n) {
    int i = blockIdx.x * blockDim.x + threadIdx.x;
    if (i >= n) return;
    float v = src[i];
    hilo(v, hi[i], lo[i]);
}

// layer-0 inputs (cat fwd+rev), emitted directly as bf16 hi/lo
__global__ void k_build_cat(const float* __restrict__ s0, const float* __restrict__ s1,
                            const float* __restrict__ s2, const float* __restrict__ s3) {
    int idx = blockIdx.x * blockDim.x + threadIdx.x;
    if (idx >= RTOK * CC) return;
    int c = idx & (CC - 1);
    int r = idx >> 9;
    int t = r & 511;
    int b = (r >> 9) & 3;
    int slot = r >> 11;
    const float* s = slot == 0 ? s0 : slot == 1 ? s1 : slot == 2 ? s2 : s3;
    int tt = t < 256 ? t : 511 - t;
    float v = s[(b * 256 + tt) * CC + c];
    hilo(v, g_ah[idx], g_al[idx]);
}

// ---------------------------------------------------------------------------
// mma.sync GEMM: C = A * W^T (bf16 hi/lo x3), 128x128 tile, BK=32,
// 2-stage cp.async double buffer, 2 CTAs/SM.
// ---------------------------------------------------------------------------
#define MM_STAGE 40960
#define MM_TILE  10240

__global__ __launch_bounds__(256, 2) void k_mma(
    const __nv_bfloat16* __restrict__ Ah, const __nv_bfloat16* __restrict__ Al,
    const __nv_bfloat16* __restrict__ WhB, const __nv_bfloat16* __restrict__ WlB,
    float* __restrict__ C, int K, int ldc,
    int rpg, int wstride, int w0, int w1, int w2, int w3) {
    extern __shared__ __align__(128) uint8_t smraw[];
    const uint32_t smb = smem_u32(smraw);
    const int tid = threadIdx.x;
    const int wid = tid >> 5;
    const int lane = tid & 31;
    const int wm = wid >> 2;
    const int wn = wid & 3;
    const int row0 = blockIdx.y * 128;
    const int col0 = blockIdx.x * 128;
    const int wsel = wsel4(row0 / rpg, w0, w1, w2, w3);
    const __nv_bfloat16* Wh = WhB + (size_t)wsel * wstride;
    const __nv_bfloat16* Wl = WlB + (size_t)wsel * wstride;
    const int nc = K >> 5;

    float acc[4][4][4];
#pragma unroll
    for (int i = 0; i < 4; i++)
#pragma unroll
        for (int j = 0; j < 4; j++)
#pragma unroll
            for (int q = 0; q < 4; q++) acc[i][j][q] = 0.f;

    auto load_stage = [&](int kc, int st) {
        const int k0 = kc << 5;
        const uint32_t sb = smb + st * MM_STAGE;
#pragma unroll
        for (int p = 0; p < 8; p++) {
            int u = tid + (p << 8);
            int tile = u >> 9;
            int v = u & 511;
            int r = v >> 2, seg = v & 3;
            const __nv_bfloat16* src;
            if (tile == 0)      src = Ah + (size_t)(row0 + r) * K;
            else if (tile == 1) src = Al + (size_t)(row0 + r) * K;
            else if (tile == 2) src = Wh + (size_t)(col0 + r) * K;
            else                src = Wl + (size_t)(col0 + r) * K;
            CP16(sb + tile * MM_TILE + r * 80 + seg * 16, src + k0 + seg * 8);
        }
        CP_COMMIT();
    };

    load_stage(0, 0);
    CP_WAIT0();
    __syncthreads();

    const uint32_t aRowByte = (uint32_t)(wm * 64 + (lane & 15)) * 80 + ((lane >> 4) << 4);
    const uint32_t bRowByte = (uint32_t)(wn * 32 + (lane & 7)) * 80 + (((lane >> 3) & 1) << 4);

    for (int c = 0; c < nc; c++) {
        const int st = c & 1;
        if (c + 1 < nc) load_stage(c + 1, st ^ 1);  // writes st^1: safe, all
                                                    // readers of st^1 synced
        const uint32_t sb = smb + st * MM_STAGE;
#pragma unroll
        for (int ks = 0; ks < 2; ks++) {
            uint32_t ah[4][4], al[4][4], bh[4][2], bl[4][2];
            const uint32_t kb = ks * 32;
#pragma unroll
            for (int mi = 0; mi < 4; mi++) {
                uint32_t ra = sb + aRowByte + (uint32_t)mi * 16 * 80 + kb;
                LDM4(ah[mi][0], ah[mi][1], ah[mi][2], ah[mi][3], ra);
                LDM4(al[mi][0], al[mi][1], al[mi][2], al[mi][3], ra + MM_TILE);
            }
#pragma unroll
            for (int ni = 0; ni < 4; ni++) {
                uint32_t rb = sb + 2 * MM_TILE + bRowByte + (uint32_t)ni * 8 * 80 + kb;
                LDM2(bh[ni][0], bh[ni][1], rb);
                LDM2(bl[ni][0], bl[ni][1], rb + MM_TILE);
            }
#pragma unroll
            for (int mi = 0; mi < 4; mi++)
#pragma unroll
                for (int ni = 0; ni < 4; ni++) {
                    MMA16816(acc[mi][ni], ah[mi], bh[ni]);
                    MMA16816(acc[mi][ni], ah[mi], bl[ni]);
                    MMA16816(acc[mi][ni], al[mi], bh[ni]);
                }
        }
        if (c + 1 < nc) CP_WAIT0();
        __syncthreads();  // all done reading st before next iter overwrites it
    }

    const int gr = lane >> 2;
    const int gc = (lane & 3) * 2;
#pragma unroll
    for (int mi = 0; mi < 4; mi++)
#pragma unroll
        for (int ni = 0; ni < 4; ni++) {
            int row = row0 + wm * 64 + mi * 16 + gr;
            int col = col0 + wn * 32 + ni * 8 + gc;
            float* p0 = C + (size_t)row * ldc + col;
            float* p1 = C + (size_t)(row + 8) * ldc + col;
            *(float2*)p0 = make_float2(acc[mi][ni][0], acc[mi][ni][1]);
            *(float2*)p1 = make_float2(acc[mi][ni][2], acc[mi][ni][3]);
        }
}

// ---------------------------------------------------------------------------
// 64x64 FFMA2 GEMM body (x_proj split-K, dt-proj)
// ---------------------------------------------------------------------------
__device__ __forceinline__ void gemm64_accum(
    const float* A, const float* W, unsigned long long acc[4][2],
    int K, int lda, int ldb, int row0, int col0) {
    __shared__ float As[16][68];
    __shared__ float Bs[16][68];
    const int tid = threadIdx.x;
    const int tx = tid & 15, ty = tid >> 4;
    for (int k0 = 0; k0 < K; k0 += 16) {
        __syncthreads();
#pragma unroll
        for (int i = 0; i < 4; i++) {
            int idx = tid + i * 256;
            int kk = idx & 15, rr = idx >> 4;
            As[kk][rr] = A[(size_t)(row0 + rr) * lda + k0 + kk];
            Bs[kk][rr] = W[(size_t)(col0 + rr) * ldb + k0 + kk];
        }
        __syncthreads();
#pragma unroll
        for (int kk = 0; kk < 16; kk++) {
            float a[4];
            *(float4*)a = *(const float4*)&As[kk][ty * 4];
            unsigned long long b2[2];
            *(float4*)b2 = *(const float4*)&Bs[kk][tx * 4];
#pragma unroll
            for (int i = 0; i < 4; i++) {
                unsigned long long ad;
                DUP2(ad, a[i]);
                FMA2(acc[i][0], ad, b2[0]);
                FMA2(acc[i][1], ad, b2[1]);
            }
        }
    }
}

__global__ __launch_bounds__(256) void k_gemm64sk(
    const float* __restrict__ A, const float* __restrict__ Wb,
    int rpg, int wstride, int w0, int w1, int w2, int w3) {
    const int row0 = blockIdx.y * 64;
    const int z = blockIdx.z;
    const int wsel = wsel4(row0 / rpg, w0, w1, w2, w3);
    const float* W = Wb + (size_t)wsel * wstride + z * 256;
    unsigned long long acc[4][2];
#pragma unroll
    for (int i = 0; i < 4; i++) { acc[i][0] = 0ull; acc[i][1] = 0ull; }
    gemm64_accum(A + z * 256, W, acc, 256, 1024, 1024, row0, 0);
    float* Cout = g_xdblp + (size_t)z * RTOK * 64;
    const int tx = threadIdx.x & 15, ty = threadIdx.x >> 4;
#pragma unroll
    for (int i = 0; i < 4; i++) {
        float* cp = Cout + (size_t)(row0 + ty * 4 + i) * 64 + tx * 4;
        *(ulonglong2*)cp = make_ulonglong2(acc[i][0], acc[i][1]);
    }
}

__global__ void k_reduce4() {
    int idx = blockIdx.x * blockDim.x + threadIdx.x;
    if (idx >= RTOK * 64) return;
    const int S = RTOK * 64;
    g_xdbl[idx] = (g_xdblp[idx] + g_xdblp[idx + S]) +
                  (g_xdblp[idx + 2 * S] + g_xdblp[idx + 3 * S]);
}

// dt-proj with fused +dtb and softplus -> g_delta
__global__ __launch_bounds__(256) void k_gemm64dt(
    const float* __restrict__ dtw, const float* __restrict__ dtb,
    int rpg, int w0, int w1, int w2, int w3) {
    const int row0 = blockIdx.y * 64;
    const int col0 = blockIdx.x * 64;
    const int m = wsel4(row0 / rpg, w0, w1, w2, w3);
    const float* W = dtw + (size_t)m * DIN * 32;
    unsigned long long acc[4][2];
#pragma unroll
    for (int i = 0; i < 4; i++) { acc[i][0] = 0ull; acc[i][1] = 0ull; }
    gemm64_accum(g_xdbl, W, acc, 32, 64, 32, row0, col0);
    const int tx = threadIdx.x & 15, ty = threadIdx.x >> 4;
#pragma unroll
    for (int i = 0; i < 4; i++) {
        const float* av = (const float*)acc[i];
        float r[4];
#pragma unroll
        for (int j = 0; j < 4; j++) {
            int col = col0 + tx * 4 + j;
            float x = av[j] + dtb[m * DIN + col];
            r[j] = (x > 15.f) ? x : __logf(1.f + __expf(x));
        }
        float* cp = g_delta + (size_t)(row0 + ty * 4 + i) * DIN + col0 + tx * 4;
        *(float4*)cp = make_float4(r[0], r[1], r[2], r[3]);
    }
}

// ---------------------------------------------------------------------------
__global__ void k_conv(const float* __restrict__ cw, const float* __restrict__ cb,
                       int T, int rpg, int w0, int w1, int w2, int w3) {
    int idx = blockIdx.x * blockDim.x + threadIdx.x;
    if (idx >= RTOK * DIN) return;
    int d = idx & (DIN - 1);
    int r = idx >> 10;
    int t = r & (T - 1);
    int m = wsel4(r / rpg, w0, w1, w2, w3);
    const float* cwp = cw + ((size_t)m * DIN + d) * 4;
    float acc = cb[m * DIN + d];
    int base = r * (2 * DIN) + d;
#pragma unroll
    for (int k = 0; k < 4; k++) {
        int tt = t - 3 + k;
        if (tt >= 0) acc = fmaf(cwp[k], g_xz[base + (k - 3) * (2 * DIN)], acc);
    }
    float e = __expf(-acc);
    g_x[idx] = __fdividef(acc, 1.f + e);
}

// ---------------------------------------------------------------------------
// selective scan: B/C rows staged through smem cp.async ring (depth 6),
// per-thread delta/x/z prefetched 3 ahead in registers; log-depth dA powers;
// writes gated y as bf16 hi/lo into g_ah/g_al.
// ---------------------------------------------------------------------------
template <bool CHAIN>
__device__ __forceinline__ void scan_body(int rbase, int T, int d, int tid,
                                          float* sring, const float Av[16], float Dv) {
    const uint32_t srb = smem_u32(sring);
    float h[16];
#pragma unroll
    for (int s = 0; s < 16; s++) h[s] = 0.f;

    // prologue: smem ring rows 0..5 (one commit each)
#pragma unroll
    for (int i = 0; i < 6; i++) {
        if (tid < 8 && i < T)
            CP16(srb + (uint32_t)(i & 7) * 128 + (uint32_t)tid * 16,
                 g_xdbl + (size_t)(rbase + i) * 64 + 32 + tid * 4);
        CP_COMMIT();
    }
    // scalar prefetch t = 0..2
    float dl[4], xl[4], zl[4];
#pragma unroll
    for (int i = 0; i < 3; i++) {
        int r = rbase + i;
        dl[i] = g_delta[(size_t)r * DIN + d];
        xl[i] = g_x[(size_t)r * DIN + d];
        zl[i] = g_xz[(size_t)r * (2 * DIN) + DIN + d];
    }

#pragma unroll 4
    for (int t = 0; t < T; t++) {
        const int cs = t & 3;
        // smem ring: issue row t+6 (empty group at tail keeps count exact)
        if (tid < 8 && t + 6 < T)
            CP16(srb + (uint32_t)((t + 6) & 7) * 128 + (uint32_t)tid * 16,
                 g_xdbl + (size_t)(rbase + t + 6) * 64 + 32 + tid * 4);
        CP_COMMIT();
        CP_WAIT6();
        __syncthreads();
        // scalar prefetch t+3
        if (t + 3 < T) {
            int r = rbase + t + 3;
            dl[(t + 3) & 3] = g_delta[(size_t)r * DIN + d];
            xl[(t + 3) & 3] = g_x[(size_t)r * DIN + d];
            zl[(t + 3) & 3] = g_xz[(size_t)r * (2 * DIN) + DIN + d];
        }
        float delta = dl[cs], xv = xl[cs], zv = zl[cs];
        const float4* bc = (const float4*)(sring + (t & 7) * 32);
        float4 Bq[4], Cq[4];
#pragma unroll
        for (int q = 0; q < 4; q++) { Bq[q] = bc[q]; Cq[q] = bc[q + 4]; }
        const float* Bv = (const float*)Bq;
        const float* Cv = (const float*)Cq;

        float dx = delta * xv;
        float p[16];
        if (CHAIN) {
            float e1 = __expf(delta * Av[0]);
            float e2 = e1 * e1, e4 = e2 * e2, e8 = e4 * e4;
            p[0] = e1;        p[1] = e2;        p[2] = e2 * e1;   p[3] = e4;
            p[4] = e4 * e1;   p[5] = e4 * e2;   p[6] = e4 * p[2]; p[7] = e8;
            p[8] = e8 * e1;   p[9] = e8 * e2;   p[10] = e8 * p[2]; p[11] = e8 * e4;
            p[12] = e8 * p[4]; p[13] = e8 * p[5]; p[14] = e8 * p[6]; p[15] = e8 * e8;
        } else {
#pragma unroll
            for (int s = 0; s < 16; s++) p[s] = __expf(delta * Av[s]);
        }
        float y0 = 0.f, y1 = 0.f, y2 = 0.f, y3 = 0.f;
#pragma unroll
        for (int s = 0; s < 16; s++) {
            h[s] = fmaf(h[s], p[s], dx * Bv[s]);
            float hv = h[s] * Cv[s];
            if ((s & 3) == 0) y0 += hv;
            else if ((s & 3) == 1) y1 += hv;
            else if ((s & 3) == 2) y2 += hv;
            else y3 += hv;
        }
        float y = (y0 + y1) + (y2 + y3);
        y = fmaf(Dv, xv, y);
        float sg = __fdividef(zv, 1.f + __expf(-zv));
        float yv = y * sg;
        int r = rbase + t;
        hilo(yv, g_ah[(size_t)r * DIN + d], g_al[(size_t)r * DIN + d]);
    }
}

__global__ __launch_bounds__(128) void k_scan(const float* __restrict__ Alog,
                                              const float* __restrict__ Dp,
                                              int T, int w0, int w1, int w2, int w3) {
    __shared__ float sring[8 * 32];
    int seq = blockIdx.x >> 3;
    int d = ((blockIdx.x & 7) << 7) | threadIdx.x;
    int m = wsel4(seq >> 2, w0, w1, w2, w3);
    float Av[16];
    const float* ap = Alog + ((size_t)m * DIN + d) * 16;
#pragma unroll
    for (int s = 0; s < 16; s++) Av[s] = -__expf(ap[s]);
    bool chain = true;
#pragma unroll
    for (int s = 1; s < 16; s++)
        chain = chain &&
                (fabsf(Av[s] - (float)(s + 1) * Av[0]) <=
                 1e-3f * (float)(s + 1) * fabsf(Av[0]) + 1e-7f);
    // chain flag is uniform across the block (A depends only on m), so the
    // branch below is block-uniform and __syncthreads inside is safe.
    float Dv = Dp[m * DIN + d];
    int rbase = seq * T;
    if (chain) scan_body<true>(rbase, T, d, threadIdx.x, sring, Av, Dv);
    else       scan_body<false>(rbase, T, d, threadIdx.x, sring, Av, Dv);
}

// ---------------------------------------------------------------------------
// layer-0 epilogue: fold halves, layernorm, residual; emit layer-1 GEMM input
// (forward + reversed copies) directly as bf16 hi/lo.
// ---------------------------------------------------------------------------
__global__ __launch_bounds__(128) void k_combine(
    const float* __restrict__ s0, const float* __restrict__ s1,
    const float* __restrict__ s2, const float* __restrict__ s3,
    const float* __restrict__ lnw, const float* __restrict__ lnb) {
    int blk = blockIdx.x;
    int t = blk & 255;
    int b = (blk >> 8) & 3;
    int slot = blk >> 10;
    const float* src = slot == 0 ? s0 : slot == 1 ? s1 : slot == 2 ? s2 : s3;
    int rowA = ((slot * 4 + b) * 512 + t) * CC;
    int rowB = ((slot * 4 + b) * 512 + (511 - t)) * CC;
    int tid = threadIdx.x;
    float v[4];
#pragma unroll
    for (int j = 0; j < 4; j++) {
        int c = tid + j * 128;
        v[j] = 0.5f * (g_o[rowA + c] + g_o[rowB + c]);
    }
    __shared__ float red[8];
    int wid = tid >> 5, lane = tid & 31;
    float s = (v[0] + v[1]) + (v[2] + v[3]);
#pragma unroll
    for (int o = 16; o; o >>= 1) s += __shfl_xor_sync(~0u, s, o);
    if (lane == 0) red[wid] = s;
    __syncthreads();
    float mean = (red[0] + red[1] + red[2] + red[3]) * (1.f / 512.f);
    float q = 0.f;
#pragma unroll
    for (int j = 0; j < 4; j++) { float dd = v[j] - mean; q = fmaf(dd, dd, q); }
#pragma unroll
    for (int o = 16; o; o >>= 1) q += __shfl_xor_sync(~0u, q, o);
    if (lane == 0) red[4 + wid] = q;
    __syncthreads();
    float var = (red[4] + red[5] + red[6] + red[7]) * (1.f / 512.f);
    float rstd = rsqrtf(var + 1e-5f);
    int tau = slot * 256 + t;
#pragma unroll
    for (int j = 0; j < 4; j++) {
        int c = tid + j * 128;
        float o = (v[j] - mean) * rstd * lnw[c] + lnb[c] + src[(b * 256 + t) * CC + c];
        __nv_bfloat16 hh, ll;
        hilo(o, hh, ll);
        int idxF = ((b * 1024) + tau) * CC + c;
        int idxR = (((4 + b) * 1024) + (1023 - tau)) * CC + c;
        g_ah[idxF] = hh; g_al[idxF] = ll;
        g_ah[idxR] = hh; g_al[idxR] = ll;
    }
}

__global__ void k_final(float* __restrict__ out) {
    int idx = blockIdx.x * blockDim.x + threadIdx.x;
    if (idx >= BB * 1024 * CC) return;
    int c = idx & (CC - 1);
    int rest = idx >> 9;
    int tau = rest & 1023;
    int b = rest >> 10;
    float f = 0.5f * (g_o[((b * 1024) + tau) * CC + c] +
                      g_o[(((4 + b) * 1024) + (1023 - tau)) * CC + c]);
    int i = tau >> 8;
    int t = tau & 255;
    out[(((i * 4 + b) * 256 + t) << 9) + c] = f;
}

// ---------------------------------------------------------------------------
extern "C" void kernel_launch(void* const* d_in, const int* in_sizes, int n_in,
                              void* d_out, int out_size) {
    const float* x0hw = (const float*)d_in[0];
    const float* x1hw = (const float*)d_in[1];
    const float* x0wh = (const float*)d_in[2];
    const float* x1wh = (const float*)d_in[3];
    const float* in_w = (const float*)d_in[4];
    const float* cw   = (const float*)d_in[5];
    const float* cb   = (const float*)d_in[6];
    const float* xw   = (const float*)d_in[7];
    const float* dtw  = (const float*)d_in[8];
    const float* dtb  = (const float*)d_in[9];
    const float* alog = (const float*)d_in[10];
    const float* Dp   = (const float*)d_in[11];
    const float* ow   = (const float*)d_in[12];
    const float* lnw  = (const float*)d_in[13];
    const float* lnb  = (const float*)d_in[14];
    float* out = (float*)d_out;

    float *pxz, *px, *po;
    cudaGetSymbolAddress((void**)&pxz, g_xz);
    cudaGetSymbolAddress((void**)&px, g_x);
    cudaGetSymbolAddress((void**)&po, g_o);
    __nv_bfloat16 *pah, *pal, *pwih, *pwil, *pwoh, *pwol;
    cudaGetSymbolAddress((void**)&pah, g_ah);
    cudaGetSymbolAddress((void**)&pal, g_al);
    cudaGetSymbolAddress((void**)&pwih, g_wih);
    cudaGetSymbolAddress((void**)&pwil, g_wil);
    cudaGetSymbolAddress((void**)&pwoh, g_woh);
    cudaGetSymbolAddress((void**)&pwol, g_wol);

    static int smem_set = 0;
    if (!smem_set) {
        cudaFuncSetAttribute(k_mma, cudaFuncAttributeMaxDynamicSharedMemorySize,
                             2 * MM_STAGE);
        smem_set = 1;
    }
    const int MMSMEM = 2 * MM_STAGE;

    const int EL = RTOK * DIN;
    const int EL2 = RTOK * CC;
    const int ELF = BB * 1024 * CC;

    // weights -> bf16 hi/lo
    k_cvt<<<(6 * 2048 * 512 + 255) / 256, 256>>>(in_w, pwih, pwil, 6 * 2048 * 512);
    k_cvt<<<(6 * 512 * 1024 + 255) / 256, 256>>>(ow, pwoh, pwol, 6 * 512 * 1024);

    // ---------------- layer 0 ----------------
    {
        const int w0 = 0, w1 = 2, w2 = 1, w3 = 3, rpg = 2048, T = 512;
        k_build_cat<<<(EL2 + 255) / 256, 256>>>(x0hw, x1hw, x0wh, x1wh);
        k_mma<<<dim3(2048 / 128, RTOK / 128), 256, MMSMEM>>>(
            pah, pal, pwih, pwil, pxz, 512, 2048, rpg, 2048 * 512, w0, w1, w2, w3);
        k_conv<<<(EL + 255) / 256, 256>>>(cw, cb, T, rpg, w0, w1, w2, w3);
        k_gemm64sk<<<dim3(1, RTOK / 64, 4), 256>>>(px, xw, rpg, 64 * 1024, w0, w1, w2, w3);
        k_reduce4<<<(RTOK * 64 + 255) / 256, 256>>>();
        k_gemm64dt<<<dim3(1024 / 64, RTOK / 64), 256>>>(dtw, dtb, rpg, w0, w1, w2, w3);
        k_scan<<<16 * 8, 128>>>(alog, Dp, T, w0, w1, w2, w3);
        k_mma<<<dim3(512 / 128, RTOK / 128), 256, MMSMEM>>>(
            pah, pal, pwoh, pwol, po, 1024, 512, rpg, 512 * 1024, w0, w1, w2, w3);
        k_combine<<<4096, 128>>>(x0hw, x1hw, x0wh, x1wh, lnw, lnb);
    }

    // ---------------- layer 1 ----------------
    {
        const int w0 = 4, w1 = 5, w2 = 4, w3 = 5, rpg = 4096, T = 1024;
        k_mma<<<dim3(2048 / 128, RTOK / 128), 256, MMSMEM>>>(
            pah, pal, pwih, pwil, pxz, 512, 2048, rpg, 2048 * 512, w0, w1, w2, w3);
        k_conv<<<(EL + 255) / 256, 256>>>(cw, cb, T, rpg, w0, w1, w2, w3);
        k_gemm64sk<<<dim3(1, RTOK / 64, 4), 256>>>(px, xw, rpg, 64 * 1024, w0, w1, w2, w3);
        k_reduce4<<<(RTOK * 64 + 255) / 256, 256>>>();
        k_gemm64dt<<<dim3(1024 / 64, RTOK / 64), 256>>>(dtw, dtb, rpg, w0, w1, w2, w3);
        k_scan<<<8 * 8, 128>>>(alog, Dp, T, w0, w1, w2, w3);
        k_mma<<<dim3(512 / 128, RTOK / 128), 256, MMSMEM>>>(
            pah, pal, pwoh, pwol, po, 1024, 512, rpg, 512 * 1024, w0, w1, w2, w3);
        k_final<<<(ELF + 255) / 256, 256>>>(out);
    }
}

// round 7
// speedup vs baseline: 2.6037x; 1.5230x over previous
#include <cuda_runtime.h>
#include <cuda_bf16.h>
#include <cstdint>

// ---------------------------------------------------------------------------
// MultiScaleMambaEncoder — mma.sync bf16 hi/lo x3 GEMMs + chunked parallel scan
// ---------------------------------------------------------------------------

#define BB 4
#define CC 512
#define DIN 1024
#define RTOK 8192

// fp32 scratch
__device__ float g_xz[RTOK * 2 * DIN];
__device__ float g_x[RTOK * DIN];          // conv output, then ylin (pass A)
__device__ float g_xdbl[RTOK * 64];
__device__ float g_xdblp[4 * RTOK * 64];   // split-K partials; reused as P-chunk
__device__ float g_hch[16 * 128 * 1024];   // per-chunk local h, then h_in
__device__ float g_delta[RTOK * DIN];
__device__ float g_o[RTOK * CC];
// bf16 hi/lo scratch (GEMM A operands)
__device__ __nv_bfloat16 g_ah[RTOK * DIN];
__device__ __nv_bfloat16 g_al[RTOK * DIN];
__device__ __nv_bfloat16 g_wih[6 * 2048 * 512];
__device__ __nv_bfloat16 g_wil[6 * 2048 * 512];
__device__ __nv_bfloat16 g_woh[6 * 512 * 1024];
__device__ __nv_bfloat16 g_wol[6 * 512 * 1024];

__device__ __forceinline__ int wsel4(int ml, int w0, int w1, int w2, int w3) {
    return ml == 0 ? w0 : ml == 1 ? w1 : ml == 2 ? w2 : w3;
}

#define FMA2(d, a, b) asm("fma.rn.f32x2 %0, %1, %2, %0;" : "+l"(d) : "l"(a), "l"(b))
#define DUP2(d, s)    asm("mov.b64 %0, {%1, %1};" : "=l"(d) : "f"(s))

__device__ __forceinline__ uint32_t smem_u32(const void* p) {
    uint32_t a;
    asm("{ .reg .u64 t; cvta.to.shared.u64 t, %1; cvt.u32.u64 %0, t; }" : "=r"(a) : "l"(p));
    return a;
}
#define CP16(dst, src)  asm volatile("cp.async.cg.shared.global [%0], [%1], 16;" :: "r"(dst), "l"(src))
#define CP_COMMIT()     asm volatile("cp.async.commit_group;" ::: "memory")
#define CP_WAIT0()      asm volatile("cp.async.wait_group 0;" ::: "memory")

#define LDM4(r0, r1, r2, r3, a) \
    asm volatile("ldmatrix.sync.aligned.m8n8.x4.shared.b16 {%0,%1,%2,%3}, [%4];" \
                 : "=r"(r0), "=r"(r1), "=r"(r2), "=r"(r3) : "r"(a))
#define LDM2(r0, r1, a) \
    asm volatile("ldmatrix.sync.aligned.m8n8.x2.shared.b16 {%0,%1}, [%2];" \
                 : "=r"(r0), "=r"(r1) : "r"(a))
#define MMA16816(d, a, b) \
    asm volatile("mma.sync.aligned.m16n8k16.row.col.f32.bf16.bf16.f32 " \
                 "{%0,%1,%2,%3},{%4,%5,%6,%7},{%8,%9},{%0,%1,%2,%3};" \
                 : "+f"((d)[0]), "+f"((d)[1]), "+f"((d)[2]), "+f"((d)[3]) \
                 : "r"((a)[0]), "r"((a)[1]), "r"((a)[2]), "r"((a)[3]), \
                   "r"((b)[0]), "r"((b)[1]))

__device__ __forceinline__ void hilo(float v, __nv_bfloat16& h, __nv_bfloat16& l) {
    h = __float2bfloat16(v);
    l = __float2bfloat16(v - __bfloat162float(h));
}

// powers: p[s] = e1^(s+1), depth-4 ladder
__device__ __forceinline__ void powers16(float e1, float* p) {
    float e2 = e1 * e1, e4 = e2 * e2, e8 = e4 * e4;
    p[0] = e1;        p[1] = e2;        p[2] = e2 * e1;   p[3] = e4;
    p[4] = e4 * e1;   p[5] = e4 * e2;   p[6] = e4 * p[2]; p[7] = e8;
    p[8] = e8 * e1;   p[9] = e8 * e2;   p[10] = e8 * p[2]; p[11] = e8 * e4;
    p[12] = e8 * p[4]; p[13] = e8 * p[5]; p[14] = e8 * p[6]; p[15] = e8 * e8;
}

// ---------------------------------------------------------------------------
__global__ void k_cvt(const float* __restrict__ src, __nv_bfloat16* __restrict__ hi,
                      __nv_bfloat16* __restrict__ lo, int n) {
    int i = blockIdx.x * blockDim.x + threadIdx.x;
    if (i >= n) return;
    float v = src[i];
    hilo(v, hi[i], lo[i]);
}

// layer-0 inputs (cat fwd+rev), emitted directly as bf16 hi/lo
__global__ void k_build_cat(const float* __restrict__ s0, const float* __restrict__ s1,
                            const float* __restrict__ s2, const float* __restrict__ s3) {
    int idx = blockIdx.x * blockDim.x + threadIdx.x;
    if (idx >= RTOK * CC) return;
    int c = idx & (CC - 1);
    int r = idx >> 9;
    int t = r & 511;
    int b = (r >> 9) & 3;
    int slot = r >> 11;
    const float* s = slot == 0 ? s0 : slot == 1 ? s1 : slot == 2 ? s2 : s3;
    int tt = t < 256 ? t : 511 - t;
    float v = s[(b * 256 + tt) * CC + c];
    hilo(v, g_ah[idx], g_al[idx]);
}

// ---------------------------------------------------------------------------
// mma.sync GEMM: C = A * W^T (bf16 hi/lo x3), 128x128 tile, BK=32,
// 2-stage cp.async double buffer, 2 CTAs/SM.
// ---------------------------------------------------------------------------
#define MM_STAGE 40960
#define MM_TILE  10240

__global__ __launch_bounds__(256, 2) void k_mma(
    const __nv_bfloat16* __restrict__ Ah, const __nv_bfloat16* __restrict__ Al,
    const __nv_bfloat16* __restrict__ WhB, const __nv_bfloat16* __restrict__ WlB,
    float* __restrict__ C, int K, int ldc,
    int rpg, int wstride, int w0, int w1, int w2, int w3) {
    extern __shared__ __align__(128) uint8_t smraw[];
    const uint32_t smb = smem_u32(smraw);
    const int tid = threadIdx.x;
    const int wid = tid >> 5;
    const int lane = tid & 31;
    const int wm = wid >> 2;
    const int wn = wid & 3;
    const int row0 = blockIdx.y * 128;
    const int col0 = blockIdx.x * 128;
    const int wsel = wsel4(row0 / rpg, w0, w1, w2, w3);
    const __nv_bfloat16* Wh = WhB + (size_t)wsel * wstride;
    const __nv_bfloat16* Wl = WlB + (size_t)wsel * wstride;
    const int nc = K >> 5;

    float acc[4][4][4];
#pragma unroll
    for (int i = 0; i < 4; i++)
#pragma unroll
        for (int j = 0; j < 4; j++)
#pragma unroll
            for (int q = 0; q < 4; q++) acc[i][j][q] = 0.f;

    auto load_stage = [&](int kc, int st) {
        const int k0 = kc << 5;
        const uint32_t sb = smb + st * MM_STAGE;
#pragma unroll
        for (int p = 0; p < 8; p++) {
            int u = tid + (p << 8);
            int tile = u >> 9;
            int v = u & 511;
            int r = v >> 2, seg = v & 3;
            const __nv_bfloat16* src;
            if (tile == 0)      src = Ah + (size_t)(row0 + r) * K;
            else if (tile == 1) src = Al + (size_t)(row0 + r) * K;
            else if (tile == 2) src = Wh + (size_t)(col0 + r) * K;
            else                src = Wl + (size_t)(col0 + r) * K;
            CP16(sb + tile * MM_TILE + r * 80 + seg * 16, src + k0 + seg * 8);
        }
        CP_COMMIT();
    };

    load_stage(0, 0);
    CP_WAIT0();
    __syncthreads();

    const uint32_t aRowByte = (uint32_t)(wm * 64 + (lane & 15)) * 80 + ((lane >> 4) << 4);
    const uint32_t bRowByte = (uint32_t)(wn * 32 + (lane & 7)) * 80 + (((lane >> 3) & 1) << 4);

    for (int c = 0; c < nc; c++) {
        const int st = c & 1;
        if (c + 1 < nc) load_stage(c + 1, st ^ 1);
        const uint32_t sb = smb + st * MM_STAGE;
#pragma unroll
        for (int ks = 0; ks < 2; ks++) {
            uint32_t ah[4][4], al[4][4], bh[4][2], bl[4][2];
            const uint32_t kb = ks * 32;
#pragma unroll
            for (int mi = 0; mi < 4; mi++) {
                uint32_t ra = sb + aRowByte + (uint32_t)mi * 16 * 80 + kb;
                LDM4(ah[mi][0], ah[mi][1], ah[mi][2], ah[mi][3], ra);
                LDM4(al[mi][0], al[mi][1], al[mi][2], al[mi][3], ra + MM_TILE);
            }
#pragma unroll
            for (int ni = 0; ni < 4; ni++) {
                uint32_t rb = sb + 2 * MM_TILE + bRowByte + (uint32_t)ni * 8 * 80 + kb;
                LDM2(bh[ni][0], bh[ni][1], rb);
                LDM2(bl[ni][0], bl[ni][1], rb + MM_TILE);
            }
#pragma unroll
            for (int mi = 0; mi < 4; mi++)
#pragma unroll
                for (int ni = 0; ni < 4; ni++) {
                    MMA16816(acc[mi][ni], ah[mi], bh[ni]);
                    MMA16816(acc[mi][ni], ah[mi], bl[ni]);
                    MMA16816(acc[mi][ni], al[mi], bh[ni]);
                }
        }
        if (c + 1 < nc) CP_WAIT0();
        __syncthreads();
    }

    const int gr = lane >> 2;
    const int gc = (lane & 3) * 2;
#pragma unroll
    for (int mi = 0; mi < 4; mi++)
#pragma unroll
        for (int ni = 0; ni < 4; ni++) {
            int row = row0 + wm * 64 + mi * 16 + gr;
            int col = col0 + wn * 32 + ni * 8 + gc;
            float* p0 = C + (size_t)row * ldc + col;
            float* p1 = C + (size_t)(row + 8) * ldc + col;
            *(float2*)p0 = make_float2(acc[mi][ni][0], acc[mi][ni][1]);
            *(float2*)p1 = make_float2(acc[mi][ni][2], acc[mi][ni][3]);
        }
}

// ---------------------------------------------------------------------------
// 64x64 FFMA2 GEMM body (x_proj split-K, dt-proj)
// ---------------------------------------------------------------------------
__device__ __forceinline__ void gemm64_accum(
    const float* A, const float* W, unsigned long long acc[4][2],
    int K, int lda, int ldb, int row0, int col0) {
    __shared__ float As[16][68];
    __shared__ float Bs[16][68];
    const int tid = threadIdx.x;
    const int tx = tid & 15, ty = tid >> 4;
    for (int k0 = 0; k0 < K; k0 += 16) {
        __syncthreads();
#pragma unroll
        for (int i = 0; i < 4; i++) {
            int idx = tid + i * 256;
            int kk = idx & 15, rr = idx >> 4;
            As[kk][rr] = A[(size_t)(row0 + rr) * lda + k0 + kk];
            Bs[kk][rr] = W[(size_t)(col0 + rr) * ldb + k0 + kk];
        }
        __syncthreads();
#pragma unroll
        for (int kk = 0; kk < 16; kk++) {
            float a[4];
            *(float4*)a = *(const float4*)&As[kk][ty * 4];
            unsigned long long b2[2];
            *(float4*)b2 = *(const float4*)&Bs[kk][tx * 4];
#pragma unroll
            for (int i = 0; i < 4; i++) {
                unsigned long long ad;
                DUP2(ad, a[i]);
                FMA2(acc[i][0], ad, b2[0]);
                FMA2(acc[i][1], ad, b2[1]);
            }
        }
    }
}

__global__ __launch_bounds__(256) void k_gemm64sk(
    const float* __restrict__ A, const float* __restrict__ Wb,
    int rpg, int wstride, int w0, int w1, int w2, int w3) {
    const int row0 = blockIdx.y * 64;
    const int z = blockIdx.z;
    const int wsel = wsel4(row0 / rpg, w0, w1, w2, w3);
    const float* W = Wb + (size_t)wsel * wstride + z * 256;
    unsigned long long acc[4][2];
#pragma unroll
    for (int i = 0; i < 4; i++) { acc[i][0] = 0ull; acc[i][1] = 0ull; }
    gemm64_accum(A + z * 256, W, acc, 256, 1024, 1024, row0, 0);
    float* Cout = g_xdblp + (size_t)z * RTOK * 64;
    const int tx = threadIdx.x & 15, ty = threadIdx.x >> 4;
#pragma unroll
    for (int i = 0; i < 4; i++) {
        float* cp = Cout + (size_t)(row0 + ty * 4 + i) * 64 + tx * 4;
        *(ulonglong2*)cp = make_ulonglong2(acc[i][0], acc[i][1]);
    }
}

__global__ void k_reduce4() {
    int idx = blockIdx.x * blockDim.x + threadIdx.x;
    if (idx >= RTOK * 64) return;
    const int S = RTOK * 64;
    g_xdbl[idx] = (g_xdblp[idx] + g_xdblp[idx + S]) +
                  (g_xdblp[idx + 2 * S] + g_xdblp[idx + 3 * S]);
}

// dt-proj with fused +dtb and softplus -> g_delta
__global__ __launch_bounds__(256) void k_gemm64dt(
    const float* __restrict__ dtw, const float* __restrict__ dtb,
    int rpg, int w0, int w1, int w2, int w3) {
    const int row0 = blockIdx.y * 64;
    const int col0 = blockIdx.x * 64;
    const int m = wsel4(row0 / rpg, w0, w1, w2, w3);
    const float* W = dtw + (size_t)m * DIN * 32;
    unsigned long long acc[4][2];
#pragma unroll
    for (int i = 0; i < 4; i++) { acc[i][0] = 0ull; acc[i][1] = 0ull; }
    gemm64_accum(g_xdbl, W, acc, 32, 64, 32, row0, col0);
    const int tx = threadIdx.x & 15, ty = threadIdx.x >> 4;
#pragma unroll
    for (int i = 0; i < 4; i++) {
        const float* av = (const float*)acc[i];
        float r[4];
#pragma unroll
        for (int j = 0; j < 4; j++) {
            int col = col0 + tx * 4 + j;
            float x = av[j] + dtb[m * DIN + col];
            r[j] = (x > 15.f) ? x : __logf(1.f + __expf(x));
        }
        float* cp = g_delta + (size_t)(row0 + ty * 4 + i) * DIN + col0 + tx * 4;
        *(float4*)cp = make_float4(r[0], r[1], r[2], r[3]);
    }
}

// ---------------------------------------------------------------------------
__global__ void k_conv(const float* __restrict__ cw, const float* __restrict__ cb,
                       int T, int rpg, int w0, int w1, int w2, int w3) {
    int idx = blockIdx.x * blockDim.x + threadIdx.x;
    if (idx >= RTOK * DIN) return;
    int d = idx & (DIN - 1);
    int r = idx >> 10;
    int t = r & (T - 1);
    int m = wsel4(r / rpg, w0, w1, w2, w3);
    const float* cwp = cw + ((size_t)m * DIN + d) * 4;
    float acc = cb[m * DIN + d];
    int base = r * (2 * DIN) + d;
#pragma unroll
    for (int k = 0; k < 4; k++) {
        int tt = t - 3 + k;
        if (tt >= 0) acc = fmaf(cwp[k], g_xz[base + (k - 3) * (2 * DIN)], acc);
    }
    float e = __expf(-acc);
    g_x[idx] = __fdividef(acc, 1.f + e);
}

// ---------------------------------------------------------------------------
// Chunked selective scan. 128 global chunks of 64 steps (both layers).
// Pass A: local scan (h0=0); ylin (incl. D*x) overwrites g_x; store h_loc, P.
// Pass B: per-(seq,d) prefix over chunks -> h_in (overwrites g_hch).
// Pass C: y = (ylin + C.(cumprod p * h_in)) * silu(z) -> bf16 hi/lo.
// ---------------------------------------------------------------------------
template <bool CHAIN>
__device__ __forceinline__ void scanA_body(int rbase, int d, int g,
                                           const float Av[16], float Dv) {
    float h[16];
#pragma unroll
    for (int s = 0; s < 16; s++) h[s] = 0.f;
    float dsum = 0.f;
#pragma unroll 2
    for (int t = 0; t < 64; t++) {
        int r = rbase + t;
        float delta = g_delta[(size_t)r * DIN + d];
        float xv = g_x[(size_t)r * DIN + d];
        const float4* bc = (const float4*)(g_xdbl + (size_t)r * 64 + 32);
        float4 Bq[4], Cq[4];
#pragma unroll
        for (int q = 0; q < 4; q++) { Bq[q] = bc[q]; Cq[q] = bc[q + 4]; }
        const float* Bv = (const float*)Bq;
        const float* Cv = (const float*)Cq;
        dsum += delta;
        float p[16];
        if (CHAIN) powers16(__expf(delta * Av[0]), p);
        else {
#pragma unroll
            for (int s = 0; s < 16; s++) p[s] = __expf(delta * Av[s]);
        }
        float dx = delta * xv;
        float y0 = 0.f, y1 = 0.f, y2 = 0.f, y3 = 0.f;
#pragma unroll
        for (int s = 0; s < 16; s++) {
            h[s] = fmaf(h[s], p[s], dx * Bv[s]);
            float hv = h[s] * Cv[s];
            if ((s & 3) == 0) y0 += hv;
            else if ((s & 3) == 1) y1 += hv;
            else if ((s & 3) == 2) y2 += hv;
            else y3 += hv;
        }
        g_x[(size_t)r * DIN + d] = fmaf(Dv, xv, (y0 + y1) + (y2 + y3));
    }
    float P[16];
    if (CHAIN) powers16(__expf(dsum * Av[0]), P);
    else {
#pragma unroll
        for (int s = 0; s < 16; s++) P[s] = __expf(dsum * Av[s]);
    }
#pragma unroll
    for (int s = 0; s < 16; s++) {
        size_t o = ((size_t)(s * 128 + g) << 10) + d;
        g_hch[o] = h[s];
        g_xdblp[o] = P[s];   // P-chunk buffer (partials are dead by now)
    }
}

__global__ __launch_bounds__(128) void k_scanA(const float* __restrict__ Alog,
                                               const float* __restrict__ Dp,
                                               int lgNCH, int w0, int w1, int w2, int w3) {
    int blk = blockIdx.x;
    int dg = blk & 7;
    int g = blk >> 3;                    // global chunk 0..127
    int seq = g >> lgNCH;
    int d = (dg << 7) | threadIdx.x;
    int m = wsel4(seq >> 2, w0, w1, w2, w3);
    float Av[16];
    const float* ap = Alog + ((size_t)m * DIN + d) * 16;
#pragma unroll
    for (int s = 0; s < 16; s++) Av[s] = -__expf(ap[s]);
    bool chain = true;
#pragma unroll
    for (int s = 1; s < 16; s++)
        chain = chain &&
                (fabsf(Av[s] - (float)(s + 1) * Av[0]) <=
                 1e-3f * (float)(s + 1) * fabsf(Av[0]) + 1e-7f);
    float Dv = Dp[m * DIN + d];
    int rbase = g << 6;
    if (chain) scanA_body<true>(rbase, d, g, Av, Dv);
    else       scanA_body<false>(rbase, d, g, Av, Dv);
}

__global__ void k_scanB(int lgNCH, int nseq) {
    int idx = blockIdx.x * blockDim.x + threadIdx.x;
    if (idx >= nseq * DIN) return;
    int seq = idx >> 10;
    int d = idx & 1023;
    int NCH = 1 << lgNCH;
    float hin[16];
#pragma unroll
    for (int s = 0; s < 16; s++) hin[s] = 0.f;
    for (int j = 0; j < NCH; j++) {
        int g = (seq << lgNCH) + j;
#pragma unroll
        for (int s = 0; s < 16; s++) {
            size_t o = ((size_t)(s * 128 + g) << 10) + d;
            float hl = g_hch[o];
            float Pp = g_xdblp[o];
            g_hch[o] = hin[s];                  // h_in for chunk j
            hin[s] = fmaf(Pp, hin[s], hl);
        }
    }
}

template <bool CHAIN>
__device__ __forceinline__ void scanC_body(int rbase, int d, int g,
                                           const float Av[16]) {
    float q[16];
#pragma unroll
    for (int s = 0; s < 16; s++)
        q[s] = g_hch[((size_t)(s * 128 + g) << 10) + d];
#pragma unroll 2
    for (int t = 0; t < 64; t++) {
        int r = rbase + t;
        float delta = g_delta[(size_t)r * DIN + d];
        float zv = g_xz[(size_t)r * 2048 + 1024 + d];
        float ylin = g_x[(size_t)r * DIN + d];
        const float4* cp = (const float4*)(g_xdbl + (size_t)r * 64 + 48);
        float4 Cq[4];
#pragma unroll
        for (int u = 0; u < 4; u++) Cq[u] = cp[u];
        const float* Cv = (const float*)Cq;
        float p[16];
        if (CHAIN) powers16(__expf(delta * Av[0]), p);
        else {
#pragma unroll
            for (int s = 0; s < 16; s++) p[s] = __expf(delta * Av[s]);
        }
        float c0 = 0.f, c1 = 0.f, c2 = 0.f, c3 = 0.f;
#pragma unroll
        for (int s = 0; s < 16; s++) {
            q[s] *= p[s];
            float hv = q[s] * Cv[s];
            if ((s & 3) == 0) c0 += hv;
            else if ((s & 3) == 1) c1 += hv;
            else if ((s & 3) == 2) c2 += hv;
            else c3 += hv;
        }
        float y = ylin + (c0 + c1) + (c2 + c3);
        float sg = __fdividef(zv, 1.f + __expf(-zv));
        float yv = y * sg;
        hilo(yv, g_ah[(size_t)r * DIN + d], g_al[(size_t)r * DIN + d]);
    }
}

__global__ __launch_bounds__(128) void k_scanC(const float* __restrict__ Alog,
                                               int lgNCH, int w0, int w1, int w2, int w3) {
    int blk = blockIdx.x;
    int dg = blk & 7;
    int g = blk >> 3;
    int seq = g >> lgNCH;
    int j = g & ((1 << lgNCH) - 1);
    int d = (dg << 7) | threadIdx.x;
    int rbase = g << 6;
    if (j == 0) {
        // h_in == 0: gate only
#pragma unroll 2
        for (int t = 0; t < 64; t++) {
            int r = rbase + t;
            float zv = g_xz[(size_t)r * 2048 + 1024 + d];
            float ylin = g_x[(size_t)r * DIN + d];
            float sg = __fdividef(zv, 1.f + __expf(-zv));
            float yv = ylin * sg;
            hilo(yv, g_ah[(size_t)r * DIN + d], g_al[(size_t)r * DIN + d]);
        }
        return;
    }
    int m = wsel4(seq >> 2, w0, w1, w2, w3);
    float Av[16];
    const float* ap = Alog + ((size_t)m * DIN + d) * 16;
#pragma unroll
    for (int s = 0; s < 16; s++) Av[s] = -__expf(ap[s]);
    bool chain = true;
#pragma unroll
    for (int s = 1; s < 16; s++)
        chain = chain &&
                (fabsf(Av[s] - (float)(s + 1) * Av[0]) <=
                 1e-3f * (float)(s + 1) * fabsf(Av[0]) + 1e-7f);
    if (chain) scanC_body<true>(rbase, d, g, Av);
    else       scanC_body<false>(rbase, d, g, Av);
}

// ---------------------------------------------------------------------------
// layer-0 epilogue: fold halves, layernorm, residual; emit layer-1 GEMM input
// (forward + reversed copies) directly as bf16 hi/lo.
// ---------------------------------------------------------------------------
__global__ __launch_bounds__(128) void k_combine(
    const float* __restrict__ s0, const float* __restrict__ s1,
    const float* __restrict__ s2, const float* __restrict__ s3,
    const float* __restrict__ lnw, const float* __restrict__ lnb) {
    int blk = blockIdx.x;
    int t = blk & 255;
    int b = (blk >> 8) & 3;
    int slot = blk >> 10;
    const float* src = slot == 0 ? s0 : slot == 1 ? s1 : slot == 2 ? s2 : s3;
    int rowA = ((slot * 4 + b) * 512 + t) * CC;
    int rowB = ((slot * 4 + b) * 512 + (511 - t)) * CC;
    int tid = threadIdx.x;
    float v[4];
#pragma unroll
    for (int j = 0; j < 4; j++) {
        int c = tid + j * 128;
        v[j] = 0.5f * (g_o[rowA + c] + g_o[rowB + c]);
    }
    __shared__ float red[8];
    int wid = tid >> 5, lane = tid & 31;
    float s = (v[0] + v[1]) + (v[2] + v[3]);
#pragma unroll
    for (int o = 16; o; o >>= 1) s += __shfl_xor_sync(~0u, s, o);
    if (lane == 0) red[wid] = s;
    __syncthreads();
    float mean = (red[0] + red[1] + red[2] + red[3]) * (1.f / 512.f);
    float q = 0.f;
#pragma unroll
    for (int j = 0; j < 4; j++) { float dd = v[j] - mean; q = fmaf(dd, dd, q); }
#pragma unroll
    for (int o = 16; o; o >>= 1) q += __shfl_xor_sync(~0u, q, o);
    if (lane == 0) red[4 + wid] = q;
    __syncthreads();
    float var = (red[4] + red[5] + red[6] + red[7]) * (1.f / 512.f);
    float rstd = rsqrtf(var + 1e-5f);
    int tau = slot * 256 + t;
#pragma unroll
    for (int j = 0; j < 4; j++) {
        int c = tid + j * 128;
        float o = (v[j] - mean) * rstd * lnw[c] + lnb[c] + src[(b * 256 + t) * CC + c];
        __nv_bfloat16 hh, ll;
        hilo(o, hh, ll);
        int idxF = ((b * 1024) + tau) * CC + c;
        int idxR = (((4 + b) * 1024) + (1023 - tau)) * CC + c;
        g_ah[idxF] = hh; g_al[idxF] = ll;
        g_ah[idxR] = hh; g_al[idxR] = ll;
    }
}

__global__ void k_final(float* __restrict__ out) {
    int idx = blockIdx.x * blockDim.x + threadIdx.x;
    if (idx >= BB * 1024 * CC) return;
    int c = idx & (CC - 1);
    int rest = idx >> 9;
    int tau = rest & 1023;
    int b = rest >> 10;
    float f = 0.5f * (g_o[((b * 1024) + tau) * CC + c] +
                      g_o[(((4 + b) * 1024) + (1023 - tau)) * CC + c]);
    int i = tau >> 8;
    int t = tau & 255;
    out[(((i * 4 + b) * 256 + t) << 9) + c] = f;
}

// ---------------------------------------------------------------------------
extern "C" void kernel_launch(void* const* d_in, const int* in_sizes, int n_in,
                              void* d_out, int out_size) {
    const float* x0hw = (const float*)d_in[0];
    const float* x1hw = (const float*)d_in[1];
    const float* x0wh = (const float*)d_in[2];
    const float* x1wh = (const float*)d_in[3];
    const float* in_w = (const float*)d_in[4];
    const float* cw   = (const float*)d_in[5];
    const float* cb   = (const float*)d_in[6];
    const float* xw   = (const float*)d_in[7];
    const float* dtw  = (const float*)d_in[8];
    const float* dtb  = (const float*)d_in[9];
    const float* alog = (const float*)d_in[10];
    const float* Dp   = (const float*)d_in[11];
    const float* ow   = (const float*)d_in[12];
    const float* lnw  = (const float*)d_in[13];
    const float* lnb  = (const float*)d_in[14];
    float* out = (float*)d_out;

    float *pxz, *px, *po;
    cudaGetSymbolAddress((void**)&pxz, g_xz);
    cudaGetSymbolAddress((void**)&px, g_x);
    cudaGetSymbolAddress((void**)&po, g_o);
    __nv_bfloat16 *pah, *pal, *pwih, *pwil, *pwoh, *pwol;
    cudaGetSymbolAddress((void**)&pah, g_ah);
    cudaGetSymbolAddress((void**)&pal, g_al);
    cudaGetSymbolAddress((void**)&pwih, g_wih);
    cudaGetSymbolAddress((void**)&pwil, g_wil);
    cudaGetSymbolAddress((void**)&pwoh, g_woh);
    cudaGetSymbolAddress((void**)&pwol, g_wol);

    static int smem_set = 0;
    if (!smem_set) {
        cudaFuncSetAttribute(k_mma, cudaFuncAttributeMaxDynamicSharedMemorySize,
                             2 * MM_STAGE);
        smem_set = 1;
    }
    const int MMSMEM = 2 * MM_STAGE;

    const int EL = RTOK * DIN;
    const int EL2 = RTOK * CC;
    const int ELF = BB * 1024 * CC;

    // weights -> bf16 hi/lo
    k_cvt<<<(6 * 2048 * 512 + 255) / 256, 256>>>(in_w, pwih, pwil, 6 * 2048 * 512);
    k_cvt<<<(6 * 512 * 1024 + 255) / 256, 256>>>(ow, pwoh, pwol, 6 * 512 * 1024);

    // ---------------- layer 0 (T=512, NCH=8, nseq=16) ----------------
    {
        const int w0 = 0, w1 = 2, w2 = 1, w3 = 3, rpg = 2048, T = 512, lg = 3, nseq = 16;
        k_build_cat<<<(EL2 + 255) / 256, 256>>>(x0hw, x1hw, x0wh, x1wh);
        k_mma<<<dim3(2048 / 128, RTOK / 128), 256, MMSMEM>>>(
            pah, pal, pwih, pwil, pxz, 512, 2048, rpg, 2048 * 512, w0, w1, w2, w3);
        k_conv<<<(EL + 255) / 256, 256>>>(cw, cb, T, rpg, w0, w1, w2, w3);
        k_gemm64sk<<<dim3(1, RTOK / 64, 4), 256>>>(px, xw, rpg, 64 * 1024, w0, w1, w2, w3);
        k_reduce4<<<(RTOK * 64 + 255) / 256, 256>>>();
        k_gemm64dt<<<dim3(1024 / 64, RTOK / 64), 256>>>(dtw, dtb, rpg, w0, w1, w2, w3);
        k_scanA<<<1024, 128>>>(alog, Dp, lg, w0, w1, w2, w3);
        k_scanB<<<(nseq * DIN + 255) / 256, 256>>>(lg, nseq);
        k_scanC<<<1024, 128>>>(alog, lg, w0, w1, w2, w3);
        k_mma<<<dim3(512 / 128, RTOK / 128), 256, MMSMEM>>>(
            pah, pal, pwoh, pwol, po, 1024, 512, rpg, 512 * 1024, w0, w1, w2, w3);
        k_combine<<<4096, 128>>>(x0hw, x1hw, x0wh, x1wh, lnw, lnb);
    }

    // ---------------- layer 1 (T=1024, NCH=16, nseq=8) ----------------
    {
        const int w0 = 4, w1 = 5, w2 = 4, w3 = 5, rpg = 4096, T = 1024, lg = 4, nseq = 8;
        k_mma<<<dim3(2048 / 128, RTOK / 128), 256, MMSMEM>>>(
            pah, pal, pwih, pwil, pxz, 512, 2048, rpg, 2048 * 512, w0, w1, w2, w3);
        k_conv<<<(EL + 255) / 256, 256>>>(cw, cb, T, rpg, w0, w1, w2, w3);
        k_gemm64sk<<<dim3(1, RTOK / 64, 4), 256>>>(px, xw, rpg, 64 * 1024, w0, w1, w2, w3);
        k_reduce4<<<(RTOK * 64 + 255) / 256, 256>>>();
        k_gemm64dt<<<dim3(1024 / 64, RTOK / 64), 256>>>(dtw, dtb, rpg, w0, w1, w2, w3);
        k_scanA<<<1024, 128>>>(alog, Dp, lg, w0, w1, w2, w3);
        k_scanB<<<(nseq * DIN + 255) / 256, 256>>>(lg, nseq);
        k_scanC<<<1024, 128>>>(alog, lg, w0, w1, w2, w3);
        k_mma<<<dim3(512 / 128, RTOK / 128), 256, MMSMEM>>>(
            pah, pal, pwoh, pwol, po, 1024, 512, rpg, 512 * 1024, w0, w1, w2, w3);
        k_final<<<(ELF + 255) / 256, 256>>>(out);
    }
}